// round 6
// baseline (speedup 1.0000x reference)
#include <cuda_runtime.h>
#include <cuda_bf16.h>
#include <math.h>
#include <stdint.h>

#define NROWS 32768
#define DIM 1024
#define NRES 21

// ---------------- scratch (no cudaMalloc allowed) ----------------
__device__ float g_act[(size_t)NROWS * DIM];
__device__ float g_h[(size_t)NROWS * DIM];
__device__ float g_ang[(size_t)NROWS * 14];
__device__ int8_t g_qa1[(size_t)NROWS * DIM];
__device__ int8_t g_qa2[(size_t)NROWS * DIM];
__device__ int8_t g_qb1[(size_t)NROWS * DIM];
__device__ int8_t g_qb2[(size_t)NROWS * DIM];
__device__ float g_sa[NROWS];
__device__ float g_sb[NROWS];
__device__ int8_t g_wq1[3][(size_t)DIM * DIM];   // transposed quantized weights [n][k]
__device__ int8_t g_wq2[3][(size_t)DIM * DIM];
__device__ float g_ws[3][DIM];
__device__ unsigned g_wmax[3][DIM];              // zero-init; atomicMax idempotent

// ---------------- PTX helpers (baseline compute_103 safe) ----------------
__device__ __forceinline__ uint32_t smem_to_u32(const void* p) {
    uint32_t a;
    asm("{ .reg .u64 t; cvta.to.shared.u64 t, %1; cvt.u32.u64 %0, t; }" : "=r"(a) : "l"(p));
    return a;
}
__device__ __forceinline__ void ldsm4(uint32_t (&r)[4], uint32_t addr) {
    asm volatile("ldmatrix.sync.aligned.m8n8.x4.shared.b16 {%0,%1,%2,%3}, [%4];"
                 : "=r"(r[0]), "=r"(r[1]), "=r"(r[2]), "=r"(r[3]) : "r"(addr));
}
__device__ __forceinline__ void mma_s8(int* d, const uint32_t* a, const uint32_t* b) {
    asm volatile(
        "mma.sync.aligned.m16n8k32.row.col.s32.s8.s8.s32 "
        "{%0,%1,%2,%3}, {%4,%5,%6,%7}, {%8,%9}, {%0,%1,%2,%3};"
        : "+r"(d[0]), "+r"(d[1]), "+r"(d[2]), "+r"(d[3])
        : "r"(a[0]), "r"(a[1]), "r"(a[2]), "r"(a[3]), "r"(b[0]), "r"(b[1]));
}
__device__ __forceinline__ void cp16(uint32_t dst, const void* src) {
    asm volatile("cp.async.cg.shared.global [%0], [%1], 16;" :: "r"(dst), "l"(src));
}
__device__ __forceinline__ void cp_commit() {
    asm volatile("cp.async.commit_group;" ::: "memory");
}
template<int N>
__device__ __forceinline__ void cp_wait() {
    asm volatile("cp.async.wait_group %0;" :: "n"(N) : "memory");
}
__device__ __forceinline__ uint32_t pack4(int a, int b, int c, int d) {
    return (uint32_t)(a & 0xff) | ((uint32_t)(b & 0xff) << 8) |
           ((uint32_t)(c & 0xff) << 16) | ((uint32_t)(d & 0xff) << 24);
}

// ---------------- int8 GEMM ----------------
// smem tile: 128 rows x 128B; units(16B): 0-3 = q1 (64 s8), 4-7 = q2.
// swizzle: unit' = unit ^ (row & 7).  KCHUNK = 64 k-elems per chunk.
#define KCHUNK 64
#define NITERS (DIM / KCHUNK)    // 16
#define TILE_S 16384
#define STAGE_S (2 * TILE_S)     // 32768
#define NSTAGE 4
#define SMEM_TOTAL (NSTAGE * STAGE_S)   // 131072

// D = SA[row]*SB[col]*(P11 + Pcross/256) + bias_scale*bias (+ C if RESID)
template<int RESID>
__global__ __launch_bounds__(256, 1) void gemm_s8(
    const int8_t* __restrict__ Aq1, const int8_t* __restrict__ Aq2,
    const float* __restrict__ SA,
    const int8_t* __restrict__ Bq1, const int8_t* __restrict__ Bq2,
    const float* __restrict__ SB,
    const float* __restrict__ bias, float bias_scale, float* __restrict__ C)
{
    extern __shared__ char smem[];
    const uint32_t sb = smem_to_u32(smem);
    const int tid = threadIdx.x;
    const int wid = tid >> 5;
    const int lane = tid & 31;
    const int bx = blockIdx.x, by = blockIdx.y;
    const int wm = wid & 3;    // warp rows: wm*32
    const int wn = wid >> 2;   // warp cols: wn*64

    int p11[2][8][4], pcx[2][8][4];
    #pragma unroll
    for (int i = 0; i < 2; i++)
        #pragma unroll
        for (int j = 0; j < 8; j++)
            #pragma unroll
            for (int q = 0; q < 4; q++) { p11[i][j][q] = 0; pcx[i][j][q] = 0; }

    // producer: 2048 x 16B per stage (A 16KB + B 16KB), 8 per thread
    auto issue = [&](int kc) {
        const int s = kc % NSTAGE;
        const uint32_t stage = sb + s * STAGE_S;
        #pragma unroll
        for (int t = 0; t < 8; t++) {
            const int i = tid + t * 256;
            const int tile = i >> 10;
            const int idx = i & 1023;
            const int row = idx >> 3;
            const int unit = idx & 7;
            const int8_t* plane;
            int grow;
            if (tile == 0) { plane = (unit < 4) ? Aq1 : Aq2; grow = by * 128 + row; }
            else           { plane = (unit < 4) ? Bq1 : Bq2; grow = bx * 128 + row; }
            const char* src = (const char*)plane + (size_t)grow * DIM
                              + kc * KCHUNK + (unit & 3) * 16;
            const uint32_t dst = stage + tile * TILE_S + row * 128
                                 + ((unit ^ (row & 7)) << 4);
            cp16(dst, src);
        }
        cp_commit();
    };

    issue(0);
    issue(1);
    issue(2);

    for (int kc = 0; kc < NITERS; kc++) {
        cp_wait<2>();
        __syncthreads();
        if (kc + 3 < NITERS) issue(kc + 3);

        const uint32_t stage = sb + (kc % NSTAGE) * STAGE_S;
        #pragma unroll
        for (int kh = 0; kh < 2; kh++) {   // two k32 sub-chunks
            uint32_t aq1[2][4], aq2[2][4];
            const int aunit = kh * 2 + (lane >> 4);
            #pragma unroll
            for (int mt = 0; mt < 2; mt++) {
                const int arow = wm * 32 + mt * 16 + (lane & 15);
                const uint32_t addr = stage + arow * 128 + ((aunit ^ (arow & 7)) << 4);
                ldsm4(aq1[mt], addr);
                ldsm4(aq2[mt], addr ^ 64);
            }
            const int bunit = kh * 2 + ((lane >> 3) & 1);
            #pragma unroll
            for (int ntp = 0; ntp < 4; ntp++) {
                const int brow = wn * 64 + ntp * 16 + (lane & 7) + (((lane >> 4) & 1) << 3);
                const uint32_t addr = stage + TILE_S + brow * 128
                                      + ((bunit ^ (brow & 7)) << 4);
                uint32_t bq1[4], bq2[4];
                ldsm4(bq1, addr);
                ldsm4(bq2, addr ^ 64);
                #pragma unroll
                for (int mt = 0; mt < 2; mt++) {
                    #pragma unroll
                    for (int c = 0; c < 2; c++) {
                        mma_s8(p11[mt][ntp * 2 + c], aq1[mt], &bq1[2 * c]);
                        mma_s8(pcx[mt][ntp * 2 + c], aq1[mt], &bq2[2 * c]);
                        mma_s8(pcx[mt][ntp * 2 + c], aq2[mt], &bq1[2 * c]);
                    }
                }
            }
        }
    }

    // epilogue
    const int rq = lane >> 2;
    const int cq = (lane & 3) * 2;
    #pragma unroll
    for (int mt = 0; mt < 2; mt++) {
        #pragma unroll
        for (int nt = 0; nt < 8; nt++) {
            const int col = bx * 128 + wn * 64 + nt * 8 + cq;
            const float sb0 = SB[col], sb1 = SB[col + 1];
            const float b0 = bias_scale * bias[col];
            const float b1 = bias_scale * bias[col + 1];
            #pragma unroll
            for (int hrow = 0; hrow < 2; hrow++) {
                const int row = by * 128 + wm * 32 + mt * 16 + rq + hrow * 8;
                const float sa = SA[row];
                float f0 = (float)p11[mt][nt][hrow * 2 + 0]
                         + (float)pcx[mt][nt][hrow * 2 + 0] * 0.00390625f;
                float f1 = (float)p11[mt][nt][hrow * 2 + 1]
                         + (float)pcx[mt][nt][hrow * 2 + 1] * 0.00390625f;
                float vx = sa * sb0 * f0 + b0;
                float vy = sa * sb1 * f1 + b1;
                float* cp = C + (size_t)row * DIM + col;
                if (RESID) {
                    float2 old = *(const float2*)cp;
                    vx += old.x; vy += old.y;
                }
                *(float2*)cp = make_float2(vx, vy);
            }
        }
    }
}

// ---------------- activation quantize: relu + per-row 2-level s8 ----------------
// DUAL: x = relu(X0)+relu(X1); else x = relu(X0). One warp per row.
template<int DUAL>
__global__ __launch_bounds__(256) void quant_act(
    const float* __restrict__ X0, const float* __restrict__ X1,
    int8_t* __restrict__ Q1, int8_t* __restrict__ Q2, float* __restrict__ S)
{
    const int row = blockIdx.x * 8 + (threadIdx.x >> 5);
    const int lane = threadIdx.x & 31;
    const float4* xr = (const float4*)(X0 + (size_t)row * DIM);
    const float4* yr = (const float4*)(X1 + (size_t)row * DIM);
    float4 v[8];
    float mx = 0.f;
    #pragma unroll
    for (int j = 0; j < 8; j++) {
        float4 a = xr[lane + j * 32];
        v[j].x = fmaxf(a.x, 0.f); v[j].y = fmaxf(a.y, 0.f);
        v[j].z = fmaxf(a.z, 0.f); v[j].w = fmaxf(a.w, 0.f);
        if (DUAL) {
            float4 b = yr[lane + j * 32];
            v[j].x += fmaxf(b.x, 0.f); v[j].y += fmaxf(b.y, 0.f);
            v[j].z += fmaxf(b.z, 0.f); v[j].w += fmaxf(b.w, 0.f);
        }
        mx = fmaxf(mx, fmaxf(fmaxf(v[j].x, v[j].y), fmaxf(v[j].z, v[j].w)));
    }
    #pragma unroll
    for (int off = 16; off; off >>= 1)
        mx = fmaxf(mx, __shfl_xor_sync(0xffffffffu, mx, off));
    const float inv = (mx > 0.f) ? (127.f / mx) : 0.f;
    if (lane == 0) S[row] = mx * (1.f / 127.f);
    uint32_t* q1o = (uint32_t*)(Q1 + (size_t)row * DIM);
    uint32_t* q2o = (uint32_t*)(Q2 + (size_t)row * DIM);
    #pragma unroll
    for (int j = 0; j < 8; j++) {
        int q1[4], q2[4];
        float e[4] = {v[j].x, v[j].y, v[j].z, v[j].w};
        #pragma unroll
        for (int q = 0; q < 4; q++) {
            float ah = e[q] * inv;
            q1[q] = __float2int_rn(ah);
            q1[q] = max(0, min(127, q1[q]));
            int r = __float2int_rn((ah - (float)q1[q]) * 256.f);
            q2[q] = max(-128, min(127, r));
        }
        q1o[lane + j * 32] = pack4(q1[0], q1[1], q1[2], q1[3]);
        q2o[lane + j * 32] = pack4(q2[0], q2[1], q2[2], q2[3]);
    }
}

// ---------------- weight col-max (|W[:,n]|), idempotent atomics ----------------
__global__ __launch_bounds__(256) void wmax_k(const float* __restrict__ W,
                                              unsigned* __restrict__ mx)
{
    const int n = blockIdx.x * 256 + threadIdx.x;
    const int k0 = blockIdx.y * 128;
    float m = 0.f;
    for (int k = k0; k < k0 + 128; k++)
        m = fmaxf(m, fabsf(W[(size_t)k * DIM + n]));
    atomicMax(&mx[n], __float_as_uint(m));
}

// ---------------- weight transpose + 2-level s8 quantize ----------------
__global__ __launch_bounds__(256) void wquant_k(
    const float* __restrict__ W, const unsigned* __restrict__ mxbits,
    int8_t* __restrict__ Q1, int8_t* __restrict__ Q2, float* __restrict__ S)
{
    __shared__ float t[32][33];
    const int n0 = blockIdx.x * 32, k0 = blockIdx.y * 32;
    const int tx = threadIdx.x, ty = threadIdx.y;  // (32, 8)
    #pragma unroll
    for (int i = 0; i < 4; i++)
        t[ty + i * 8][tx] = W[(size_t)(k0 + ty + i * 8) * DIM + n0 + tx];
    __syncthreads();
    #pragma unroll
    for (int i = 0; i < 4; i++) {
        const int n = n0 + ty + i * 8;
        const int k = k0 + tx;
        const float m = __uint_as_float(mxbits[n]);
        const float inv = (m > 0.f) ? (127.f / m) : 0.f;
        float w = t[tx][ty + i * 8] * inv;
        int q1 = __float2int_rn(w);
        q1 = max(-127, min(127, q1));
        int q2 = __float2int_rn((w - (float)q1) * 256.f);
        q2 = max(-128, min(127, q2));
        Q1[(size_t)n * DIM + k] = (int8_t)q1;
        Q2[(size_t)n * DIM + k] = (int8_t)q2;
        if (k0 == 0 && tx == 0) S[n] = m * (1.f / 127.f);
    }
}

// ---------------- torsion head ----------------
__global__ __launch_bounds__(256) void ang_kernel(
    const float* __restrict__ act, const float* __restrict__ w_ang,
    const float* __restrict__ b_ang, float* __restrict__ angbuf)
{
    const int gw = (int)((blockIdx.x * blockDim.x + threadIdx.x) >> 5);
    const int lane = threadIdx.x & 31;
    if (gw >= NROWS) return;
    const float* row = act + (size_t)gw * DIM;
    float acc[14] = {};
    for (int i = lane; i < DIM; i += 32) {
        float a = fmaxf(row[i], 0.f);
        const float* w = w_ang + i * 14;
        #pragma unroll
        for (int j = 0; j < 14; j++) acc[j] = fmaf(a, w[j], acc[j]);
    }
    #pragma unroll
    for (int j = 0; j < 14; j++) {
        #pragma unroll
        for (int off = 16; off; off >>= 1)
            acc[j] += __shfl_down_sync(0xffffffffu, acc[j], off);
    }
    if (lane == 0) {
        float* o = angbuf + (size_t)gw * 14;
        #pragma unroll
        for (int j = 0; j < 14; j++) o[j] = acc[j] + b_ang[j];
    }
}

// ---------------- per-residue geometry ----------------
__global__ __launch_bounds__(128) void epilogue_kernel(
    const float* __restrict__ angbuf,
    const float* __restrict__ rigids, const float* __restrict__ def_frames,
    const float* __restrict__ lit_pos, const float* __restrict__ atom_mask,
    const int* __restrict__ aatype, const int* __restrict__ gidx,
    float* __restrict__ out_angles, float* __restrict__ out_pred,
    float* __restrict__ out_frames)
{
    const int n = blockIdx.x * blockDim.x + threadIdx.x;
    if (n >= NROWS) return;
    const int aa = aatype[n];

    float s[8], c[8];
    s[0] = 0.f; c[0] = 1.f;
    #pragma unroll
    for (int i = 0; i < 7; i++) {
        float ss = angbuf[(size_t)n * 14 + 2 * i];
        float cc = angbuf[(size_t)n * 14 + 2 * i + 1];
        float inv = rsqrtf(fmaxf(ss * ss + cc * cc, 1e-12f));
        ss *= inv; cc *= inv;
        s[i + 1] = ss; c[i + 1] = cc;
        out_angles[(size_t)n * 14 + 2 * i] = ss;
        out_angles[(size_t)n * 14 + 2 * i + 1] = cc;
    }

    float FR[8][9], FT[8][3];
    #pragma unroll
    for (int k = 0; k < 8; k++) {
        const float* D = def_frames + ((size_t)aa * 8 + k) * 16;
        #pragma unroll
        for (int r = 0; r < 3; r++) {
            float d1 = D[r * 4 + 1], d2 = D[r * 4 + 2];
            FR[k][r * 3 + 0] = D[r * 4 + 0];
            FR[k][r * 3 + 1] = c[k] * d1 + s[k] * d2;
            FR[k][r * 3 + 2] = -s[k] * d1 + c[k] * d2;
            FT[k][r] = D[r * 4 + 3];
        }
    }

    #pragma unroll
    for (int k = 5; k <= 7; k++) {
        float R[9], T[3];
        #pragma unroll
        for (int r = 0; r < 3; r++) {
            #pragma unroll
            for (int cc2 = 0; cc2 < 3; cc2++)
                R[r * 3 + cc2] = FR[k - 1][r * 3 + 0] * FR[k][0 + cc2]
                               + FR[k - 1][r * 3 + 1] * FR[k][3 + cc2]
                               + FR[k - 1][r * 3 + 2] * FR[k][6 + cc2];
            T[r] = FR[k - 1][r * 3 + 0] * FT[k][0]
                 + FR[k - 1][r * 3 + 1] * FT[k][1]
                 + FR[k - 1][r * 3 + 2] * FT[k][2] + FT[k - 1][r];
        }
        #pragma unroll
        for (int q = 0; q < 9; q++) FR[k][q] = R[q];
        FT[k][0] = T[0]; FT[k][1] = T[1]; FT[k][2] = T[2];
    }

    const float* rg = rigids + (size_t)n * 16;
    float R0[9] = {rg[0], rg[1], rg[2], rg[4], rg[5], rg[6], rg[8], rg[9], rg[10]};
    float t0[3] = {rg[3], rg[7], rg[11]};

    #pragma unroll
    for (int k = 0; k < 8; k++) {
        float R[9], T[3];
        #pragma unroll
        for (int r = 0; r < 3; r++) {
            #pragma unroll
            for (int cc2 = 0; cc2 < 3; cc2++)
                R[r * 3 + cc2] = R0[r * 3 + 0] * FR[k][0 + cc2]
                               + R0[r * 3 + 1] * FR[k][3 + cc2]
                               + R0[r * 3 + 2] * FR[k][6 + cc2];
            T[r] = R0[r * 3 + 0] * FT[k][0] + R0[r * 3 + 1] * FT[k][1]
                 + R0[r * 3 + 2] * FT[k][2] + t0[r];
        }
        #pragma unroll
        for (int q = 0; q < 9; q++) FR[k][q] = R[q];
        FT[k][0] = T[0]; FT[k][1] = T[1]; FT[k][2] = T[2];

        float* of = out_frames + ((size_t)n * 8 + k) * 16;
        of[0]  = R[0]; of[1]  = R[1]; of[2]  = R[2]; of[3]  = T[0];
        of[4]  = R[3]; of[5]  = R[4]; of[6]  = R[5]; of[7]  = T[1];
        of[8]  = R[6]; of[9]  = R[7]; of[10] = R[8]; of[11] = T[2];
        of[12] = 0.f;  of[13] = 0.f;  of[14] = 0.f;  of[15] = 1.f;
    }

    #pragma unroll
    for (int a = 0; a < 14; a++) {
        int g = gidx[aa * 14 + a];
        const float* p = lit_pos + ((size_t)aa * 14 + a) * 3;
        float m = atom_mask[aa * 14 + a];
        float px = p[0], py = p[1], pz = p[2];
        float* op = out_pred + ((size_t)n * 14 + a) * 3;
        op[0] = (FR[g][0] * px + FR[g][1] * py + FR[g][2] * pz + FT[g][0]) * m;
        op[1] = (FR[g][3] * px + FR[g][4] * py + FR[g][5] * pz + FT[g][1]) * m;
        op[2] = (FR[g][6] * px + FR[g][7] * py + FR[g][8] * pz + FT[g][2]) * m;
    }
}

// ---------------- launch ----------------
extern "C" void kernel_launch(void* const* d_in, const int* in_sizes, int n_in,
                              void* d_out, int out_size)
{
    const float* rep0       = (const float*)d_in[0];
    const float* rep1       = (const float*)d_in[1];
    const float* w_in       = (const float*)d_in[2];
    const float* b_in       = (const float*)d_in[3];
    const float* w1         = (const float*)d_in[4];
    const float* b1         = (const float*)d_in[5];
    const float* w2         = (const float*)d_in[6];
    const float* b2         = (const float*)d_in[7];
    const float* w_ang      = (const float*)d_in[8];
    const float* b_ang      = (const float*)d_in[9];
    const float* rigids     = (const float*)d_in[10];
    const float* def_frames = (const float*)d_in[11];
    const float* lit_pos    = (const float*)d_in[12];
    const float* atom_mask  = (const float*)d_in[13];
    const int*   aatype     = (const int*)d_in[14];
    const int*   gidx       = (const int*)d_in[15];

    float *act, *h, *angb, *sa, *sbuf, *ws;
    int8_t *qa1, *qa2, *qb1, *qb2, *wq1, *wq2;
    unsigned *wmax;
    cudaGetSymbolAddress((void**)&act, g_act);
    cudaGetSymbolAddress((void**)&h, g_h);
    cudaGetSymbolAddress((void**)&angb, g_ang);
    cudaGetSymbolAddress((void**)&sa, g_sa);
    cudaGetSymbolAddress((void**)&sbuf, g_sb);
    cudaGetSymbolAddress((void**)&ws, g_ws);
    cudaGetSymbolAddress((void**)&qa1, g_qa1);
    cudaGetSymbolAddress((void**)&qa2, g_qa2);
    cudaGetSymbolAddress((void**)&qb1, g_qb1);
    cudaGetSymbolAddress((void**)&qb2, g_qb2);
    cudaGetSymbolAddress((void**)&wq1, g_wq1);
    cudaGetSymbolAddress((void**)&wq2, g_wq2);
    cudaGetSymbolAddress((void**)&wmax, g_wmax);
    const size_t WSZ = (size_t)DIM * DIM;

    cudaFuncSetAttribute(gemm_s8<0>, cudaFuncAttributeMaxDynamicSharedMemorySize, SMEM_TOTAL);
    cudaFuncSetAttribute(gemm_s8<1>, cudaFuncAttributeMaxDynamicSharedMemorySize, SMEM_TOTAL);

    // weight prep: colmax (idempotent) + transpose-quantize
    dim3 mg(DIM / 256, 8);
    wmax_k<<<mg, 256>>>(w_in, wmax + 0 * DIM);
    wmax_k<<<mg, 256>>>(w1,   wmax + 1 * DIM);
    wmax_k<<<mg, 256>>>(w2,   wmax + 2 * DIM);
    dim3 qg(DIM / 32, DIM / 32), qb(32, 8);
    wquant_k<<<qg, qb>>>(w_in, wmax + 0 * DIM, wq1 + 0 * WSZ, wq2 + 0 * WSZ, ws + 0 * DIM);
    wquant_k<<<qg, qb>>>(w1,   wmax + 1 * DIM, wq1 + 1 * WSZ, wq2 + 1 * WSZ, ws + 1 * DIM);
    wquant_k<<<qg, qb>>>(w2,   wmax + 2 * DIM, wq1 + 2 * WSZ, wq2 + 2 * WSZ, ws + 2 * DIM);

    // input: quantize relu(rep0)+relu(rep1) -> qa
    quant_act<1><<<NROWS / 8, 256>>>(rep0, rep1, qa1, qa2, sa);

    dim3 grid(DIM / 128, NROWS / 128);  // (8, 256)

    // G1: act = qa @ w_in^T + 2*b_in
    gemm_s8<0><<<grid, 256, SMEM_TOTAL>>>(qa1, qa2, sa, wq1 + 0*WSZ, wq2 + 0*WSZ,
                                          ws + 0*DIM, b_in, 2.f, act);
    // recycle 1
    quant_act<0><<<NROWS / 8, 256>>>(act, act, qb1, qb2, sbuf);
    gemm_s8<0><<<grid, 256, SMEM_TOTAL>>>(qb1, qb2, sbuf, wq1 + 1*WSZ, wq2 + 1*WSZ,
                                          ws + 1*DIM, b1, 1.f, h);
    quant_act<0><<<NROWS / 8, 256>>>(h, h, qa1, qa2, sa);
    gemm_s8<1><<<grid, 256, SMEM_TOTAL>>>(qa1, qa2, sa, wq1 + 2*WSZ, wq2 + 2*WSZ,
                                          ws + 2*DIM, b2, 1.f, act);
    // recycle 2
    quant_act<0><<<NROWS / 8, 256>>>(act, act, qb1, qb2, sbuf);
    gemm_s8<0><<<grid, 256, SMEM_TOTAL>>>(qb1, qb2, sbuf, wq1 + 1*WSZ, wq2 + 1*WSZ,
                                          ws + 1*DIM, b1, 1.f, h);
    quant_act<0><<<NROWS / 8, 256>>>(h, h, qa1, qa2, sa);
    gemm_s8<1><<<grid, 256, SMEM_TOTAL>>>(qa1, qa2, sa, wq1 + 2*WSZ, wq2 + 2*WSZ,
                                          ws + 2*DIM, b2, 1.f, act);

    ang_kernel<<<NROWS / 8, 256>>>(act, w_ang, b_ang, angb);

    float* out = (float*)d_out;
    float* out_angles = out;
    float* out_pred   = out + (size_t)NROWS * 14;
    float* out_frames = out + (size_t)NROWS * 56;
    epilogue_kernel<<<(NROWS + 127) / 128, 128>>>(
        angb, rigids, def_frames, lit_pos, atom_mask, aatype, gidx,
        out_angles, out_pred, out_frames);
}

// round 7
// speedup vs baseline: 2.7874x; 2.7874x over previous
#include <cuda_runtime.h>
#include <cuda_bf16.h>
#include <math.h>
#include <stdint.h>

#define NROWS 32768
#define DIM 1024
#define NRES 21

// ---------------- scratch (no cudaMalloc allowed) ----------------
__device__ float g_act[(size_t)NROWS * DIM];
__device__ float g_ang[(size_t)NROWS * 14];
__device__ __nv_bfloat16 g_wt_hi[3][(size_t)DIM * DIM];  // transposed weights [n][k]
__device__ __nv_bfloat16 g_wt_lo[3][(size_t)DIM * DIM];
__device__ __nv_bfloat16 g_sa_hi[(size_t)NROWS * DIM];   // activation split ping
__device__ __nv_bfloat16 g_sa_lo[(size_t)NROWS * DIM];
__device__ __nv_bfloat16 g_sb_hi[(size_t)NROWS * DIM];   // activation split pong
__device__ __nv_bfloat16 g_sb_lo[(size_t)NROWS * DIM];

// ---------------- PTX helpers (baseline compute_103 safe) ----------------
__device__ __forceinline__ uint32_t smem_to_u32(const void* p) {
    uint32_t a;
    asm("{ .reg .u64 t; cvta.to.shared.u64 t, %1; cvt.u32.u64 %0, t; }" : "=r"(a) : "l"(p));
    return a;
}
__device__ __forceinline__ void ldsm4(uint32_t (&r)[4], uint32_t addr) {
    asm volatile("ldmatrix.sync.aligned.m8n8.x4.shared.b16 {%0,%1,%2,%3}, [%4];"
                 : "=r"(r[0]), "=r"(r[1]), "=r"(r[2]), "=r"(r[3]) : "r"(addr));
}
// NOTE: non-volatile — dataflow through accumulator regs keeps ordering correct,
// and ptxas is free to interleave MMAs with later ldmatrix issues.
__device__ __forceinline__ void mma_bf16(float* d, const uint32_t* a, const uint32_t* b) {
    asm("mma.sync.aligned.m16n8k16.row.col.f32.bf16.bf16.f32 "
        "{%0,%1,%2,%3}, {%4,%5,%6,%7}, {%8,%9}, {%0,%1,%2,%3};"
        : "+f"(d[0]), "+f"(d[1]), "+f"(d[2]), "+f"(d[3])
        : "r"(a[0]), "r"(a[1]), "r"(a[2]), "r"(a[3]), "r"(b[0]), "r"(b[1]));
}
__device__ __forceinline__ void cp16(uint32_t dst, const void* src) {
    asm volatile("cp.async.cg.shared.global [%0], [%1], 16;" :: "r"(dst), "l"(src));
}
__device__ __forceinline__ void cp_commit() {
    asm volatile("cp.async.commit_group;" ::: "memory");
}
template<int N>
__device__ __forceinline__ void cp_wait() {
    asm volatile("cp.async.wait_group %0;" :: "n"(N) : "memory");
}
__device__ __forceinline__ uint32_t pack_bf16(__nv_bfloat16 x, __nv_bfloat16 y) {
    __nv_bfloat162 t; t.x = x; t.y = y;
    return *(uint32_t*)&t;
}

// ---------------- GEMM: pre-split bf16, cp.async 3-stage ----------------
// smem tile: 128 rows x 128 bytes. units(16B): 0-3 = hi (32 bf16), 4-7 = lo.
// swizzle: unit' = unit ^ (row & 7)
#define KCHUNK 32
#define NITERS (DIM / KCHUNK)
#define TILE_S 16384            // 128 * 128B
#define STAGE_S (2 * TILE_S)
#define NSTAGE 3
#define SMEM_TOTAL (NSTAGE * STAGE_S)   // 98304

// RESID: C += previous C;  WC: write fp32 C;  WSPLIT: write relu-split hi/lo
template<int RESID, int WC, int WSPLIT>
__global__ __launch_bounds__(256, 2) void gemm_mma(
    const __nv_bfloat16* __restrict__ Ahi, const __nv_bfloat16* __restrict__ Alo,
    const __nv_bfloat16* __restrict__ Bhi, const __nv_bfloat16* __restrict__ Blo,
    const float* __restrict__ bias, float bias_scale,
    float* __restrict__ C,
    __nv_bfloat16* __restrict__ Shi, __nv_bfloat16* __restrict__ Slo)
{
    extern __shared__ char smem[];
    const uint32_t sb = smem_to_u32(smem);
    const int tid = threadIdx.x;
    const int wid = tid >> 5;
    const int lane = tid & 31;
    const int bx = blockIdx.x, by = blockIdx.y;
    const int wm = wid & 3;    // warp rows: wm*32
    const int wn = wid >> 2;   // warp cols: wn*64

    float d[2][8][4];
    #pragma unroll
    for (int i = 0; i < 2; i++)
        #pragma unroll
        for (int j = 0; j < 8; j++)
            #pragma unroll
            for (int q = 0; q < 4; q++) d[i][j][q] = 0.f;

    // producer: 2048 x 16B per stage, 8 per thread
    auto issue = [&](int kc) {
        const int s = kc % NSTAGE;
        const uint32_t stage = sb + s * STAGE_S;
        #pragma unroll
        for (int t = 0; t < 8; t++) {
            const int i = tid + t * 256;
            const int tile = i >> 10;
            const int idx = i & 1023;
            const int row = idx >> 3;
            const int unit = idx & 7;
            const __nv_bfloat16* plane;
            int grow;
            if (tile == 0) { plane = (unit < 4) ? Ahi : Alo; grow = by * 128 + row; }
            else           { plane = (unit < 4) ? Bhi : Blo; grow = bx * 128 + row; }
            const char* src = (const char*)plane + (size_t)grow * (DIM * 2)
                              + kc * 64 + (unit & 3) * 16;
            const uint32_t dst = stage + tile * TILE_S + row * 128
                                 + ((unit ^ (row & 7)) << 4);
            cp16(dst, src);
        }
        cp_commit();
    };

    issue(0);
    issue(1);

    for (int kc = 0; kc < NITERS; kc++) {
        cp_wait<1>();
        __syncthreads();
        if (kc + 2 < NITERS) issue(kc + 2);

        const uint32_t stage = sb + (kc % NSTAGE) * STAGE_S;
        #pragma unroll
        for (int kh = 0; kh < 2; kh++) {
            // A fragments (hi & lo) for both m-tiles
            uint32_t ah[2][4], al[2][4];
            const int aunit = kh * 2 + (lane >> 4);
            #pragma unroll
            for (int mt = 0; mt < 2; mt++) {
                const int arow = wm * 32 + mt * 16 + (lane & 15);
                const uint32_t hiaddr = stage + arow * 128 + ((aunit ^ (arow & 7)) << 4);
                ldsm4(ah[mt], hiaddr);
                ldsm4(al[mt], hiaddr ^ 64);
            }
            const int bunit = kh * 2 + ((lane >> 3) & 1);
            const int brlane = (lane & 7) + (((lane >> 4) & 1) << 3);
            auto baddr = [&](int ntp) {
                const int brow = wn * 64 + ntp * 16 + brlane;
                return stage + TILE_S + brow * 128 + ((bunit ^ (brow & 7)) << 4);
            };
            // B double-buffered across ntp groups
            uint32_t bh[2][4], bl[4];
            ldsm4(bh[0], baddr(0));
            #pragma unroll
            for (int ntp = 0; ntp < 4; ntp++) {
                const int cur = ntp & 1;
                ldsm4(bl, baddr(ntp) ^ 64);        // lo plane of current group
                if (ntp < 3) ldsm4(bh[cur ^ 1], baddr(ntp + 1));  // prefetch next hi
                // 8 MMAs that need only bh[cur] first (covers bl latency)
                #pragma unroll
                for (int mt = 0; mt < 2; mt++) {
                    #pragma unroll
                    for (int c = 0; c < 2; c++) {
                        float* dd = d[mt][ntp * 2 + c];
                        mma_bf16(dd, ah[mt], &bh[cur][2 * c]);   // hh
                        mma_bf16(dd, al[mt], &bh[cur][2 * c]);   // lh
                    }
                }
                // 4 MMAs that need bl
                #pragma unroll
                for (int mt = 0; mt < 2; mt++) {
                    #pragma unroll
                    for (int c = 0; c < 2; c++) {
                        mma_bf16(d[mt][ntp * 2 + c], ah[mt], &bl[2 * c]);  // hl
                    }
                }
            }
        }
    }

    // ---- epilogue ----
    const int rq = lane >> 2;
    const int cq = (lane & 3) * 2;
    #pragma unroll
    for (int mt = 0; mt < 2; mt++) {
        #pragma unroll
        for (int nt = 0; nt < 8; nt++) {
            const int col = bx * 128 + wn * 64 + nt * 8 + cq;
            const float b0 = bias_scale * bias[col];
            const float b1 = bias_scale * bias[col + 1];
            #pragma unroll
            for (int hrow = 0; hrow < 2; hrow++) {
                const int row = by * 128 + wm * 32 + mt * 16 + rq + hrow * 8;
                float vx = d[mt][nt][hrow * 2 + 0] + b0;
                float vy = d[mt][nt][hrow * 2 + 1] + b1;
                float* cp = C + (size_t)row * DIM + col;
                if (RESID) {
                    float2 old = *(const float2*)cp;
                    vx += old.x; vy += old.y;
                }
                if (WC) *(float2*)cp = make_float2(vx, vy);
                if (WSPLIT) {
                    float rx = fmaxf(vx, 0.f), ry = fmaxf(vy, 0.f);
                    __nv_bfloat16 hx = __float2bfloat16(rx);
                    __nv_bfloat16 hy = __float2bfloat16(ry);
                    float lx = rx - __bfloat162float(hx);
                    float ly = ry - __bfloat162float(hy);
                    const size_t o = (size_t)row * DIM + col;
                    *(uint32_t*)(Shi + o) = pack_bf16(hx, hy);
                    *(uint32_t*)(Slo + o) = pack_bf16(__float2bfloat16(lx),
                                                      __float2bfloat16(ly));
                }
            }
        }
    }
}

// ---------------- fuse0: split(relu(rep0)+relu(rep1)) -> bf16 hi/lo ----------------
__global__ __launch_bounds__(256) void fuse0(
    const float* __restrict__ rep0, const float* __restrict__ rep1,
    __nv_bfloat16* __restrict__ Shi, __nv_bfloat16* __restrict__ Slo)
{
    const size_t i = ((size_t)blockIdx.x * blockDim.x + threadIdx.x) * 4;
    float4 a = *(const float4*)(rep0 + i);
    float4 b = *(const float4*)(rep1 + i);
    float v[4] = {fmaxf(a.x, 0.f) + fmaxf(b.x, 0.f),
                  fmaxf(a.y, 0.f) + fmaxf(b.y, 0.f),
                  fmaxf(a.z, 0.f) + fmaxf(b.z, 0.f),
                  fmaxf(a.w, 0.f) + fmaxf(b.w, 0.f)};
    uint32_t hi[2], lo[2];
    #pragma unroll
    for (int q = 0; q < 2; q++) {
        __nv_bfloat16 hx = __float2bfloat16(v[2*q]);
        __nv_bfloat16 hy = __float2bfloat16(v[2*q+1]);
        float lx = v[2*q] - __bfloat162float(hx);
        float ly = v[2*q+1] - __bfloat162float(hy);
        hi[q] = pack_bf16(hx, hy);
        lo[q] = pack_bf16(__float2bfloat16(lx), __float2bfloat16(ly));
    }
    *(uint2*)(Shi + i) = make_uint2(hi[0], hi[1]);
    *(uint2*)(Slo + i) = make_uint2(lo[0], lo[1]);
}

// ---------------- weight transpose + bf16 split ----------------
__global__ __launch_bounds__(256) void prep_w(const float* __restrict__ W,
                                              __nv_bfloat16* __restrict__ Whi,
                                              __nv_bfloat16* __restrict__ Wlo)
{
    __shared__ float t[32][33];
    const int n0 = blockIdx.x * 32, k0 = blockIdx.y * 32;
    const int tx = threadIdx.x, ty = threadIdx.y;  // (32, 8)
    #pragma unroll
    for (int i = 0; i < 4; i++)
        t[ty + i * 8][tx] = W[(size_t)(k0 + ty + i * 8) * DIM + n0 + tx];
    __syncthreads();
    #pragma unroll
    for (int i = 0; i < 4; i++) {
        float v = t[tx][ty + i * 8];
        __nv_bfloat16 hi = __float2bfloat16(v);
        float lo = v - __bfloat162float(hi);
        size_t o = (size_t)(n0 + ty + i * 8) * DIM + k0 + tx;
        Whi[o] = hi;
        Wlo[o] = __float2bfloat16(lo);
    }
}

// ---------------- torsion head ----------------
__global__ __launch_bounds__(256) void ang_kernel(
    const float* __restrict__ act, const float* __restrict__ w_ang,
    const float* __restrict__ b_ang, float* __restrict__ angbuf)
{
    const int gw = (int)((blockIdx.x * blockDim.x + threadIdx.x) >> 5);
    const int lane = threadIdx.x & 31;
    if (gw >= NROWS) return;
    const float* row = act + (size_t)gw * DIM;
    float acc[14] = {};
    for (int i = lane; i < DIM; i += 32) {
        float a = fmaxf(row[i], 0.f);
        const float* w = w_ang + i * 14;
        #pragma unroll
        for (int j = 0; j < 14; j++) acc[j] = fmaf(a, w[j], acc[j]);
    }
    #pragma unroll
    for (int j = 0; j < 14; j++) {
        #pragma unroll
        for (int off = 16; off; off >>= 1)
            acc[j] += __shfl_down_sync(0xffffffffu, acc[j], off);
    }
    if (lane == 0) {
        float* o = angbuf + (size_t)gw * 14;
        #pragma unroll
        for (int j = 0; j < 14; j++) o[j] = acc[j] + b_ang[j];
    }
}

// ---------------- per-residue geometry ----------------
__global__ __launch_bounds__(128) void epilogue_kernel(
    const float* __restrict__ angbuf,
    const float* __restrict__ rigids, const float* __restrict__ def_frames,
    const float* __restrict__ lit_pos, const float* __restrict__ atom_mask,
    const int* __restrict__ aatype, const int* __restrict__ gidx,
    float* __restrict__ out_angles, float* __restrict__ out_pred,
    float* __restrict__ out_frames)
{
    const int n = blockIdx.x * blockDim.x + threadIdx.x;
    if (n >= NROWS) return;
    const int aa = aatype[n];

    float s[8], c[8];
    s[0] = 0.f; c[0] = 1.f;
    #pragma unroll
    for (int i = 0; i < 7; i++) {
        float ss = angbuf[(size_t)n * 14 + 2 * i];
        float cc = angbuf[(size_t)n * 14 + 2 * i + 1];
        float inv = rsqrtf(fmaxf(ss * ss + cc * cc, 1e-12f));
        ss *= inv; cc *= inv;
        s[i + 1] = ss; c[i + 1] = cc;
        out_angles[(size_t)n * 14 + 2 * i] = ss;
        out_angles[(size_t)n * 14 + 2 * i + 1] = cc;
    }

    float FR[8][9], FT[8][3];
    #pragma unroll
    for (int k = 0; k < 8; k++) {
        const float* D = def_frames + ((size_t)aa * 8 + k) * 16;
        #pragma unroll
        for (int r = 0; r < 3; r++) {
            float d1 = D[r * 4 + 1], d2 = D[r * 4 + 2];
            FR[k][r * 3 + 0] = D[r * 4 + 0];
            FR[k][r * 3 + 1] = c[k] * d1 + s[k] * d2;
            FR[k][r * 3 + 2] = -s[k] * d1 + c[k] * d2;
            FT[k][r] = D[r * 4 + 3];
        }
    }

    #pragma unroll
    for (int k = 5; k <= 7; k++) {
        float R[9], T[3];
        #pragma unroll
        for (int r = 0; r < 3; r++) {
            #pragma unroll
            for (int cc2 = 0; cc2 < 3; cc2++)
                R[r * 3 + cc2] = FR[k - 1][r * 3 + 0] * FR[k][0 + cc2]
                               + FR[k - 1][r * 3 + 1] * FR[k][3 + cc2]
                               + FR[k - 1][r * 3 + 2] * FR[k][6 + cc2];
            T[r] = FR[k - 1][r * 3 + 0] * FT[k][0]
                 + FR[k - 1][r * 3 + 1] * FT[k][1]
                 + FR[k - 1][r * 3 + 2] * FT[k][2] + FT[k - 1][r];
        }
        #pragma unroll
        for (int q = 0; q < 9; q++) FR[k][q] = R[q];
        FT[k][0] = T[0]; FT[k][1] = T[1]; FT[k][2] = T[2];
    }

    const float* rg = rigids + (size_t)n * 16;
    float R0[9] = {rg[0], rg[1], rg[2], rg[4], rg[5], rg[6], rg[8], rg[9], rg[10]};
    float t0[3] = {rg[3], rg[7], rg[11]};

    #pragma unroll
    for (int k = 0; k < 8; k++) {
        float R[9], T[3];
        #pragma unroll
        for (int r = 0; r < 3; r++) {
            #pragma unroll
            for (int cc2 = 0; cc2 < 3; cc2++)
                R[r * 3 + cc2] = R0[r * 3 + 0] * FR[k][0 + cc2]
                               + R0[r * 3 + 1] * FR[k][3 + cc2]
                               + R0[r * 3 + 2] * FR[k][6 + cc2];
            T[r] = R0[r * 3 + 0] * FT[k][0] + R0[r * 3 + 1] * FT[k][1]
                 + R0[r * 3 + 2] * FT[k][2] + t0[r];
        }
        #pragma unroll
        for (int q = 0; q < 9; q++) FR[k][q] = R[q];
        FT[k][0] = T[0]; FT[k][1] = T[1]; FT[k][2] = T[2];

        float* of = out_frames + ((size_t)n * 8 + k) * 16;
        of[0]  = R[0]; of[1]  = R[1]; of[2]  = R[2]; of[3]  = T[0];
        of[4]  = R[3]; of[5]  = R[4]; of[6]  = R[5]; of[7]  = T[1];
        of[8]  = R[6]; of[9]  = R[7]; of[10] = R[8]; of[11] = T[2];
        of[12] = 0.f;  of[13] = 0.f;  of[14] = 0.f;  of[15] = 1.f;
    }

    #pragma unroll
    for (int a = 0; a < 14; a++) {
        int g = gidx[aa * 14 + a];
        const float* p = lit_pos + ((size_t)aa * 14 + a) * 3;
        float m = atom_mask[aa * 14 + a];
        float px = p[0], py = p[1], pz = p[2];
        float* op = out_pred + ((size_t)n * 14 + a) * 3;
        op[0] = (FR[g][0] * px + FR[g][1] * py + FR[g][2] * pz + FT[g][0]) * m;
        op[1] = (FR[g][3] * px + FR[g][4] * py + FR[g][5] * pz + FT[g][1]) * m;
        op[2] = (FR[g][6] * px + FR[g][7] * py + FR[g][8] * pz + FT[g][2]) * m;
    }
}

// ---------------- launch ----------------
extern "C" void kernel_launch(void* const* d_in, const int* in_sizes, int n_in,
                              void* d_out, int out_size)
{
    const float* rep0       = (const float*)d_in[0];
    const float* rep1       = (const float*)d_in[1];
    const float* w_in       = (const float*)d_in[2];
    const float* b_in       = (const float*)d_in[3];
    const float* w1         = (const float*)d_in[4];
    const float* b1         = (const float*)d_in[5];
    const float* w2         = (const float*)d_in[6];
    const float* b2         = (const float*)d_in[7];
    const float* w_ang      = (const float*)d_in[8];
    const float* b_ang      = (const float*)d_in[9];
    const float* rigids     = (const float*)d_in[10];
    const float* def_frames = (const float*)d_in[11];
    const float* lit_pos    = (const float*)d_in[12];
    const float* atom_mask  = (const float*)d_in[13];
    const int*   aatype     = (const int*)d_in[14];
    const int*   gidx       = (const int*)d_in[15];

    float *act, *angb;
    __nv_bfloat16 *wth, *wtl, *sah, *sal, *sbh, *sbl;
    cudaGetSymbolAddress((void**)&act, g_act);
    cudaGetSymbolAddress((void**)&angb, g_ang);
    cudaGetSymbolAddress((void**)&wth, g_wt_hi);
    cudaGetSymbolAddress((void**)&wtl, g_wt_lo);
    cudaGetSymbolAddress((void**)&sah, g_sa_hi);
    cudaGetSymbolAddress((void**)&sal, g_sa_lo);
    cudaGetSymbolAddress((void**)&sbh, g_sb_hi);
    cudaGetSymbolAddress((void**)&sbl, g_sb_lo);
    const size_t WSZ = (size_t)DIM * DIM;

    cudaFuncSetAttribute(gemm_mma<0,1,1>, cudaFuncAttributeMaxDynamicSharedMemorySize, SMEM_TOTAL);
    cudaFuncSetAttribute(gemm_mma<0,0,1>, cudaFuncAttributeMaxDynamicSharedMemorySize, SMEM_TOTAL);
    cudaFuncSetAttribute(gemm_mma<1,1,1>, cudaFuncAttributeMaxDynamicSharedMemorySize, SMEM_TOTAL);
    cudaFuncSetAttribute(gemm_mma<1,1,0>, cudaFuncAttributeMaxDynamicSharedMemorySize, SMEM_TOTAL);

    dim3 pg(DIM / 32, DIM / 32), pb(32, 8);
    prep_w<<<pg, pb>>>(w_in, wth + 0 * WSZ, wtl + 0 * WSZ);
    prep_w<<<pg, pb>>>(w1,   wth + 1 * WSZ, wtl + 1 * WSZ);
    prep_w<<<pg, pb>>>(w2,   wth + 2 * WSZ, wtl + 2 * WSZ);

    fuse0<<<(NROWS * DIM) / (256 * 4), 256>>>(rep0, rep1, sah, sal);

    dim3 grid(DIM / 128, NROWS / 128);  // (8, 256)

    // G1: act = split_in @ w_in^T + 2*b_in ; write act + split(relu(act)) -> sb
    gemm_mma<0,1,1><<<grid, 256, SMEM_TOTAL>>>(sah, sal, wth + 0*WSZ, wtl + 0*WSZ,
                                               b_in, 2.f, act, sbh, sbl);
    // G2: split(relu(sb @ w1^T + b1)) -> sa  (no fp32 h)
    gemm_mma<0,0,1><<<grid, 256, SMEM_TOTAL>>>(sbh, sbl, wth + 1*WSZ, wtl + 1*WSZ,
                                               b1, 1.f, act /*unused*/, sah, sal);
    // G3: act += sa @ w2^T + b2 ; write act + split(relu(act)) -> sb
    gemm_mma<1,1,1><<<grid, 256, SMEM_TOTAL>>>(sah, sal, wth + 2*WSZ, wtl + 2*WSZ,
                                               b2, 1.f, act, sbh, sbl);
    // G4
    gemm_mma<0,0,1><<<grid, 256, SMEM_TOTAL>>>(sbh, sbl, wth + 1*WSZ, wtl + 1*WSZ,
                                               b1, 1.f, act /*unused*/, sah, sal);
    // G5: act += sa @ w2^T + b2
    gemm_mma<1,1,0><<<grid, 256, SMEM_TOTAL>>>(sah, sal, wth + 2*WSZ, wtl + 2*WSZ,
                                               b2, 1.f, act, sbh, sbl);

    ang_kernel<<<NROWS / 8, 256>>>(act, w_ang, b_ang, angb);

    float* out = (float*)d_out;
    float* out_angles = out;
    float* out_pred   = out + (size_t)NROWS * 14;
    float* out_frames = out + (size_t)NROWS * 56;
    epilogue_kernel<<<(NROWS + 127) / 128, 128>>>(
        angb, rigids, def_frames, lit_pos, atom_mask, aatype, gidx,
        out_angles, out_pred, out_frames);
}

// round 8
// speedup vs baseline: 3.8060x; 1.3654x over previous
#include <cuda_runtime.h>
#include <cuda_fp16.h>
#include <math.h>
#include <stdint.h>

#define NROWS 32768
#define DIM 1024
#define NRES 21

// ---------------- scratch (no cudaMalloc allowed) ----------------
__device__ float g_act[(size_t)NROWS * DIM];
__device__ float g_ang[(size_t)NROWS * 14];
__device__ __half g_wt[3][(size_t)DIM * DIM];       // transposed fp16 weights [n][k]
__device__ __half g_sa_hi[(size_t)NROWS * DIM];     // activation split ping
__device__ __half g_sa_lo[(size_t)NROWS * DIM];
__device__ __half g_sb_hi[(size_t)NROWS * DIM];     // activation split pong
__device__ __half g_sb_lo[(size_t)NROWS * DIM];

// ---------------- PTX helpers (baseline compute_103 safe) ----------------
__device__ __forceinline__ uint32_t smem_to_u32(const void* p) {
    uint32_t a;
    asm("{ .reg .u64 t; cvta.to.shared.u64 t, %1; cvt.u32.u64 %0, t; }" : "=r"(a) : "l"(p));
    return a;
}
__device__ __forceinline__ void ldsm4(uint32_t (&r)[4], uint32_t addr) {
    asm volatile("ldmatrix.sync.aligned.m8n8.x4.shared.b16 {%0,%1,%2,%3}, [%4];"
                 : "=r"(r[0]), "=r"(r[1]), "=r"(r[2]), "=r"(r[3]) : "r"(addr));
}
__device__ __forceinline__ void mma_f16(float* d, const uint32_t* a, const uint32_t* b) {
    asm("mma.sync.aligned.m16n8k16.row.col.f32.f16.f16.f32 "
        "{%0,%1,%2,%3}, {%4,%5,%6,%7}, {%8,%9}, {%0,%1,%2,%3};"
        : "+f"(d[0]), "+f"(d[1]), "+f"(d[2]), "+f"(d[3])
        : "r"(a[0]), "r"(a[1]), "r"(a[2]), "r"(a[3]), "r"(b[0]), "r"(b[1]));
}
__device__ __forceinline__ void cp16(uint32_t dst, const void* src) {
    asm volatile("cp.async.cg.shared.global [%0], [%1], 16;" :: "r"(dst), "l"(src));
}
__device__ __forceinline__ void cp_commit() {
    asm volatile("cp.async.commit_group;" ::: "memory");
}
template<int N>
__device__ __forceinline__ void cp_wait() {
    asm volatile("cp.async.wait_group %0;" :: "n"(N) : "memory");
}
__device__ __forceinline__ uint32_t pack_h2(__half x, __half y) {
    __half2 t; t.x = x; t.y = y;
    return *(uint32_t*)&t;
}

// ---------------- GEMM: A pre-split fp16 (hi|lo), B single fp16 plane ----------------
// A smem tile: 128 rows x 128B; units 0-3 = hi (32 fp16), 4-7 = lo.
// B smem tile: 128 rows x 128B; units 0-3 = data (32 fp16), 4-7 unused (pad).
// swizzle: unit' = unit ^ (row & 7)
#define KCHUNK 32
#define NITERS (DIM / KCHUNK)
#define TILE_S 16384
#define STAGE_S (2 * TILE_S)    // A tile + B tile
#define NSTAGE 3
#define SMEM_TOTAL (NSTAGE * STAGE_S)   // 98304

// RESID: C += previous C;  WC: write fp32 C;  WSPLIT: write relu-split fp16 hi/lo
template<int RESID, int WC, int WSPLIT>
__global__ __launch_bounds__(256, 2) void gemm_mma(
    const __half* __restrict__ Ahi, const __half* __restrict__ Alo,
    const __half* __restrict__ Bh,
    const float* __restrict__ bias, float bias_scale,
    float* __restrict__ C,
    __half* __restrict__ Shi, __half* __restrict__ Slo)
{
    extern __shared__ char smem[];
    const uint32_t sb = smem_to_u32(smem);
    const int tid = threadIdx.x;
    const int wid = tid >> 5;
    const int lane = tid & 31;
    const int bx = blockIdx.x, by = blockIdx.y;
    const int wm = wid & 3;    // warp rows: wm*32
    const int wn = wid >> 2;   // warp cols: wn*64

    float d[2][8][4];
    #pragma unroll
    for (int i = 0; i < 2; i++)
        #pragma unroll
        for (int j = 0; j < 8; j++)
            #pragma unroll
            for (int q = 0; q < 4; q++) d[i][j][q] = 0.f;

    // producer: A 1024 units + B 512 units = 1536 x 16B per stage, 6 per thread
    auto issue = [&](int kc) {
        const int s = kc % NSTAGE;
        const uint32_t stage = sb + s * STAGE_S;
        #pragma unroll
        for (int t = 0; t < 6; t++) {
            const int i = tid + t * 256;
            const char* src;
            uint32_t dst;
            if (i < 1024) {            // A tile: hi|lo combined
                const int row = i >> 3;
                const int unit = i & 7;
                const __half* plane = (unit < 4) ? Ahi : Alo;
                src = (const char*)plane + (size_t)(by * 128 + row) * (DIM * 2)
                      + kc * 64 + (unit & 3) * 16;
                dst = stage + row * 128 + ((unit ^ (row & 7)) << 4);
            } else {                   // B tile: units 0-3 only
                const int j = i - 1024;
                const int row = j >> 2;
                const int unit = j & 3;
                src = (const char*)Bh + (size_t)(bx * 128 + row) * (DIM * 2)
                      + kc * 64 + unit * 16;
                dst = stage + TILE_S + row * 128 + ((unit ^ (row & 7)) << 4);
            }
            cp16(dst, src);
        }
        cp_commit();
    };

    issue(0);
    issue(1);

    for (int kc = 0; kc < NITERS; kc++) {
        cp_wait<1>();
        __syncthreads();
        if (kc + 2 < NITERS) issue(kc + 2);

        const uint32_t stage = sb + (kc % NSTAGE) * STAGE_S;
        #pragma unroll
        for (int kh = 0; kh < 2; kh++) {
            uint32_t ah[2][4], al[2][4];
            const int aunit = kh * 2 + (lane >> 4);
            #pragma unroll
            for (int mt = 0; mt < 2; mt++) {
                const int arow = wm * 32 + mt * 16 + (lane & 15);
                const uint32_t hiaddr = stage + arow * 128 + ((aunit ^ (arow & 7)) << 4);
                ldsm4(ah[mt], hiaddr);
                ldsm4(al[mt], hiaddr ^ 64);   // lo plane: unit+4 -> addr^64
            }
            const int bunit = kh * 2 + ((lane >> 3) & 1);
            #pragma unroll
            for (int ntp = 0; ntp < 4; ntp++) {
                const int brow = wn * 64 + ntp * 16 + (lane & 7) + (((lane >> 4) & 1) << 3);
                const uint32_t baddr = stage + TILE_S + brow * 128
                                       + ((bunit ^ (brow & 7)) << 4);
                uint32_t bh[4];
                ldsm4(bh, baddr);
                #pragma unroll
                for (int mt = 0; mt < 2; mt++) {
                    #pragma unroll
                    for (int c = 0; c < 2; c++) {
                        float* dd = d[mt][ntp * 2 + c];
                        mma_f16(dd, ah[mt], &bh[2 * c]);   // hi * B
                        mma_f16(dd, al[mt], &bh[2 * c]);   // lo * B
                    }
                }
            }
        }
    }

    // ---- epilogue ----
    const int rq = lane >> 2;
    const int cq = (lane & 3) * 2;
    #pragma unroll
    for (int mt = 0; mt < 2; mt++) {
        #pragma unroll
        for (int nt = 0; nt < 8; nt++) {
            const int col = bx * 128 + wn * 64 + nt * 8 + cq;
            const float b0 = bias_scale * bias[col];
            const float b1 = bias_scale * bias[col + 1];
            #pragma unroll
            for (int hrow = 0; hrow < 2; hrow++) {
                const int row = by * 128 + wm * 32 + mt * 16 + rq + hrow * 8;
                float vx = d[mt][nt][hrow * 2 + 0] + b0;
                float vy = d[mt][nt][hrow * 2 + 1] + b1;
                float* cp = C + (size_t)row * DIM + col;
                if (RESID) {
                    float2 old = *(const float2*)cp;
                    vx += old.x; vy += old.y;
                }
                if (WC) *(float2*)cp = make_float2(vx, vy);
                if (WSPLIT) {
                    float rx = fmaxf(vx, 0.f), ry = fmaxf(vy, 0.f);
                    __half hx = __float2half(rx);
                    __half hy = __float2half(ry);
                    __half lx = __float2half(rx - __half2float(hx));
                    __half ly = __float2half(ry - __half2float(hy));
                    const size_t o = (size_t)row * DIM + col;
                    *(uint32_t*)(Shi + o) = pack_h2(hx, hy);
                    *(uint32_t*)(Slo + o) = pack_h2(lx, ly);
                }
            }
        }
    }
}

// ---------------- fuse0: split(relu(rep0)+relu(rep1)) -> fp16 hi/lo ----------------
__global__ __launch_bounds__(256) void fuse0(
    const float* __restrict__ rep0, const float* __restrict__ rep1,
    __half* __restrict__ Shi, __half* __restrict__ Slo)
{
    const size_t i = ((size_t)blockIdx.x * blockDim.x + threadIdx.x) * 4;
    float4 a = *(const float4*)(rep0 + i);
    float4 b = *(const float4*)(rep1 + i);
    float v[4] = {fmaxf(a.x, 0.f) + fmaxf(b.x, 0.f),
                  fmaxf(a.y, 0.f) + fmaxf(b.y, 0.f),
                  fmaxf(a.z, 0.f) + fmaxf(b.z, 0.f),
                  fmaxf(a.w, 0.f) + fmaxf(b.w, 0.f)};
    uint32_t hi[2], lo[2];
    #pragma unroll
    for (int q = 0; q < 2; q++) {
        __half hx = __float2half(v[2*q]);
        __half hy = __float2half(v[2*q+1]);
        __half lx = __float2half(v[2*q]   - __half2float(hx));
        __half ly = __float2half(v[2*q+1] - __half2float(hy));
        hi[q] = pack_h2(hx, hy);
        lo[q] = pack_h2(lx, ly);
    }
    *(uint2*)(Shi + i) = make_uint2(hi[0], hi[1]);
    *(uint2*)(Slo + i) = make_uint2(lo[0], lo[1]);
}

// ---------------- weight transpose to fp16: Wt[n][k] = f16(W[k][n]) ----------------
__global__ __launch_bounds__(256) void prep_w(const float* __restrict__ W,
                                              __half* __restrict__ Wt)
{
    __shared__ float t[32][33];
    const int n0 = blockIdx.x * 32, k0 = blockIdx.y * 32;
    const int tx = threadIdx.x, ty = threadIdx.y;  // (32, 8)
    #pragma unroll
    for (int i = 0; i < 4; i++)
        t[ty + i * 8][tx] = W[(size_t)(k0 + ty + i * 8) * DIM + n0 + tx];
    __syncthreads();
    #pragma unroll
    for (int i = 0; i < 4; i++)
        Wt[(size_t)(n0 + ty + i * 8) * DIM + k0 + tx] = __float2half(t[tx][ty + i * 8]);
}

// ---------------- torsion head ----------------
__global__ __launch_bounds__(256) void ang_kernel(
    const float* __restrict__ act, const float* __restrict__ w_ang,
    const float* __restrict__ b_ang, float* __restrict__ angbuf)
{
    const int gw = (int)((blockIdx.x * blockDim.x + threadIdx.x) >> 5);
    const int lane = threadIdx.x & 31;
    if (gw >= NROWS) return;
    const float* row = act + (size_t)gw * DIM;
    float acc[14] = {};
    for (int i = lane; i < DIM; i += 32) {
        float a = fmaxf(row[i], 0.f);
        const float* w = w_ang + i * 14;
        #pragma unroll
        for (int j = 0; j < 14; j++) acc[j] = fmaf(a, w[j], acc[j]);
    }
    #pragma unroll
    for (int j = 0; j < 14; j++) {
        #pragma unroll
        for (int off = 16; off; off >>= 1)
            acc[j] += __shfl_down_sync(0xffffffffu, acc[j], off);
    }
    if (lane == 0) {
        float* o = angbuf + (size_t)gw * 14;
        #pragma unroll
        for (int j = 0; j < 14; j++) o[j] = acc[j] + b_ang[j];
    }
}

// ---------------- per-residue geometry ----------------
__global__ __launch_bounds__(128) void epilogue_kernel(
    const float* __restrict__ angbuf,
    const float* __restrict__ rigids, const float* __restrict__ def_frames,
    const float* __restrict__ lit_pos, const float* __restrict__ atom_mask,
    const int* __restrict__ aatype, const int* __restrict__ gidx,
    float* __restrict__ out_angles, float* __restrict__ out_pred,
    float* __restrict__ out_frames)
{
    const int n = blockIdx.x * blockDim.x + threadIdx.x;
    if (n >= NROWS) return;
    const int aa = aatype[n];

    float s[8], c[8];
    s[0] = 0.f; c[0] = 1.f;
    #pragma unroll
    for (int i = 0; i < 7; i++) {
        float ss = angbuf[(size_t)n * 14 + 2 * i];
        float cc = angbuf[(size_t)n * 14 + 2 * i + 1];
        float inv = rsqrtf(fmaxf(ss * ss + cc * cc, 1e-12f));
        ss *= inv; cc *= inv;
        s[i + 1] = ss; c[i + 1] = cc;
        out_angles[(size_t)n * 14 + 2 * i] = ss;
        out_angles[(size_t)n * 14 + 2 * i + 1] = cc;
    }

    float FR[8][9], FT[8][3];
    #pragma unroll
    for (int k = 0; k < 8; k++) {
        const float* D = def_frames + ((size_t)aa * 8 + k) * 16;
        #pragma unroll
        for (int r = 0; r < 3; r++) {
            float d1 = D[r * 4 + 1], d2 = D[r * 4 + 2];
            FR[k][r * 3 + 0] = D[r * 4 + 0];
            FR[k][r * 3 + 1] = c[k] * d1 + s[k] * d2;
            FR[k][r * 3 + 2] = -s[k] * d1 + c[k] * d2;
            FT[k][r] = D[r * 4 + 3];
        }
    }

    #pragma unroll
    for (int k = 5; k <= 7; k++) {
        float R[9], T[3];
        #pragma unroll
        for (int r = 0; r < 3; r++) {
            #pragma unroll
            for (int cc2 = 0; cc2 < 3; cc2++)
                R[r * 3 + cc2] = FR[k - 1][r * 3 + 0] * FR[k][0 + cc2]
                               + FR[k - 1][r * 3 + 1] * FR[k][3 + cc2]
                               + FR[k - 1][r * 3 + 2] * FR[k][6 + cc2];
            T[r] = FR[k - 1][r * 3 + 0] * FT[k][0]
                 + FR[k - 1][r * 3 + 1] * FT[k][1]
                 + FR[k - 1][r * 3 + 2] * FT[k][2] + FT[k - 1][r];
        }
        #pragma unroll
        for (int q = 0; q < 9; q++) FR[k][q] = R[q];
        FT[k][0] = T[0]; FT[k][1] = T[1]; FT[k][2] = T[2];
    }

    const float* rg = rigids + (size_t)n * 16;
    float R0[9] = {rg[0], rg[1], rg[2], rg[4], rg[5], rg[6], rg[8], rg[9], rg[10]};
    float t0[3] = {rg[3], rg[7], rg[11]};

    #pragma unroll
    for (int k = 0; k < 8; k++) {
        float R[9], T[3];
        #pragma unroll
        for (int r = 0; r < 3; r++) {
            #pragma unroll
            for (int cc2 = 0; cc2 < 3; cc2++)
                R[r * 3 + cc2] = R0[r * 3 + 0] * FR[k][0 + cc2]
                               + R0[r * 3 + 1] * FR[k][3 + cc2]
                               + R0[r * 3 + 2] * FR[k][6 + cc2];
            T[r] = R0[r * 3 + 0] * FT[k][0] + R0[r * 3 + 1] * FT[k][1]
                 + R0[r * 3 + 2] * FT[k][2] + t0[r];
        }
        #pragma unroll
        for (int q = 0; q < 9; q++) FR[k][q] = R[q];
        FT[k][0] = T[0]; FT[k][1] = T[1]; FT[k][2] = T[2];

        float* of = out_frames + ((size_t)n * 8 + k) * 16;
        of[0]  = R[0]; of[1]  = R[1]; of[2]  = R[2]; of[3]  = T[0];
        of[4]  = R[3]; of[5]  = R[4]; of[6]  = R[5]; of[7]  = T[1];
        of[8]  = R[6]; of[9]  = R[7]; of[10] = R[8]; of[11] = T[2];
        of[12] = 0.f;  of[13] = 0.f;  of[14] = 0.f;  of[15] = 1.f;
    }

    #pragma unroll
    for (int a = 0; a < 14; a++) {
        int g = gidx[aa * 14 + a];
        const float* p = lit_pos + ((size_t)aa * 14 + a) * 3;
        float m = atom_mask[aa * 14 + a];
        float px = p[0], py = p[1], pz = p[2];
        float* op = out_pred + ((size_t)n * 14 + a) * 3;
        op[0] = (FR[g][0] * px + FR[g][1] * py + FR[g][2] * pz + FT[g][0]) * m;
        op[1] = (FR[g][3] * px + FR[g][4] * py + FR[g][5] * pz + FT[g][1]) * m;
        op[2] = (FR[g][6] * px + FR[g][7] * py + FR[g][8] * pz + FT[g][2]) * m;
    }
}

// ---------------- launch ----------------
extern "C" void kernel_launch(void* const* d_in, const int* in_sizes, int n_in,
                              void* d_out, int out_size)
{
    const float* rep0       = (const float*)d_in[0];
    const float* rep1       = (const float*)d_in[1];
    const float* w_in       = (const float*)d_in[2];
    const float* b_in       = (const float*)d_in[3];
    const float* w1         = (const float*)d_in[4];
    const float* b1         = (const float*)d_in[5];
    const float* w2         = (const float*)d_in[6];
    const float* b2         = (const float*)d_in[7];
    const float* w_ang      = (const float*)d_in[8];
    const float* b_ang      = (const float*)d_in[9];
    const float* rigids     = (const float*)d_in[10];
    const float* def_frames = (const float*)d_in[11];
    const float* lit_pos    = (const float*)d_in[12];
    const float* atom_mask  = (const float*)d_in[13];
    const int*   aatype     = (const int*)d_in[14];
    const int*   gidx       = (const int*)d_in[15];

    float *act, *angb;
    __half *wt, *sah, *sal, *sbh, *sbl;
    cudaGetSymbolAddress((void**)&act, g_act);
    cudaGetSymbolAddress((void**)&angb, g_ang);
    cudaGetSymbolAddress((void**)&wt, g_wt);
    cudaGetSymbolAddress((void**)&sah, g_sa_hi);
    cudaGetSymbolAddress((void**)&sal, g_sa_lo);
    cudaGetSymbolAddress((void**)&sbh, g_sb_hi);
    cudaGetSymbolAddress((void**)&sbl, g_sb_lo);
    const size_t WSZ = (size_t)DIM * DIM;

    cudaFuncSetAttribute(gemm_mma<0,1,1>, cudaFuncAttributeMaxDynamicSharedMemorySize, SMEM_TOTAL);
    cudaFuncSetAttribute(gemm_mma<0,0,1>, cudaFuncAttributeMaxDynamicSharedMemorySize, SMEM_TOTAL);
    cudaFuncSetAttribute(gemm_mma<1,1,1>, cudaFuncAttributeMaxDynamicSharedMemorySize, SMEM_TOTAL);
    cudaFuncSetAttribute(gemm_mma<1,1,0>, cudaFuncAttributeMaxDynamicSharedMemorySize, SMEM_TOTAL);

    dim3 pg(DIM / 32, DIM / 32), pb(32, 8);
    prep_w<<<pg, pb>>>(w_in, wt + 0 * WSZ);
    prep_w<<<pg, pb>>>(w1,   wt + 1 * WSZ);
    prep_w<<<pg, pb>>>(w2,   wt + 2 * WSZ);

    fuse0<<<(NROWS * DIM) / (256 * 4), 256>>>(rep0, rep1, sah, sal);

    dim3 grid(DIM / 128, NROWS / 128);  // (8, 256)

    // G1: act = split_in @ w_in^T + 2*b_in ; also split(relu(act)) -> sb
    gemm_mma<0,1,1><<<grid, 256, SMEM_TOTAL>>>(sah, sal, wt + 0*WSZ,
                                               b_in, 2.f, act, sbh, sbl);
    // G2: split(relu(sb @ w1^T + b1)) -> sa
    gemm_mma<0,0,1><<<grid, 256, SMEM_TOTAL>>>(sbh, sbl, wt + 1*WSZ,
                                               b1, 1.f, act /*unused*/, sah, sal);
    // G3: act += sa @ w2^T + b2 ; split(relu(act)) -> sb
    gemm_mma<1,1,1><<<grid, 256, SMEM_TOTAL>>>(sah, sal, wt + 2*WSZ,
                                               b2, 1.f, act, sbh, sbl);
    // G4
    gemm_mma<0,0,1><<<grid, 256, SMEM_TOTAL>>>(sbh, sbl, wt + 1*WSZ,
                                               b1, 1.f, act /*unused*/, sah, sal);
    // G5: act += sa @ w2^T + b2
    gemm_mma<1,1,0><<<grid, 256, SMEM_TOTAL>>>(sah, sal, wt + 2*WSZ,
                                               b2, 1.f, act, sbh, sbl);

    ang_kernel<<<NROWS / 8, 256>>>(act, w_ang, b_ang, angb);

    float* out = (float*)d_out;
    float* out_angles = out;
    float* out_pred   = out + (size_t)NROWS * 14;
    float* out_frames = out + (size_t)NROWS * 56;
    epilogue_kernel<<<(NROWS + 127) / 128, 128>>>(
        angb, rigids, def_frames, lit_pos, atom_mask, aatype, gidx,
        out_angles, out_pred, out_frames);
}

// round 9
// speedup vs baseline: 4.4449x; 1.1679x over previous
#include <cuda_runtime.h>
#include <cuda_fp16.h>
#include <math.h>
#include <stdint.h>

#define NROWS 32768
#define DIM 1024
#define NRES 21

// ---------------- scratch (no cudaMalloc allowed) ----------------
__device__ float g_act[(size_t)NROWS * DIM];
__device__ float g_ang[(size_t)NROWS * 14];
__device__ __half g_wt[3][(size_t)DIM * DIM];       // transposed fp16 weights [n][k]
__device__ __half g_sa_hi[(size_t)NROWS * DIM];     // activation split ping
__device__ __half g_sa_lo[(size_t)NROWS * DIM];
__device__ __half g_sb_hi[(size_t)NROWS * DIM];     // activation split pong (hi only used)
__device__ __half g_sb_lo[(size_t)NROWS * DIM];

// ---------------- PTX helpers (baseline compute_103 safe) ----------------
__device__ __forceinline__ uint32_t smem_to_u32(const void* p) {
    uint32_t a;
    asm("{ .reg .u64 t; cvta.to.shared.u64 t, %1; cvt.u32.u64 %0, t; }" : "=r"(a) : "l"(p));
    return a;
}
__device__ __forceinline__ void ldsm4(uint32_t (&r)[4], uint32_t addr) {
    asm volatile("ldmatrix.sync.aligned.m8n8.x4.shared.b16 {%0,%1,%2,%3}, [%4];"
                 : "=r"(r[0]), "=r"(r[1]), "=r"(r[2]), "=r"(r[3]) : "r"(addr));
}
__device__ __forceinline__ void mma_f16(float* d, const uint32_t* a, const uint32_t* b) {
    asm("mma.sync.aligned.m16n8k16.row.col.f32.f16.f16.f32 "
        "{%0,%1,%2,%3}, {%4,%5,%6,%7}, {%8,%9}, {%0,%1,%2,%3};"
        : "+f"(d[0]), "+f"(d[1]), "+f"(d[2]), "+f"(d[3])
        : "r"(a[0]), "r"(a[1]), "r"(a[2]), "r"(a[3]), "r"(b[0]), "r"(b[1]));
}
__device__ __forceinline__ void cp16(uint32_t dst, const void* src) {
    asm volatile("cp.async.cg.shared.global [%0], [%1], 16;" :: "r"(dst), "l"(src));
}
__device__ __forceinline__ void cp_commit() {
    asm volatile("cp.async.commit_group;" ::: "memory");
}
template<int N>
__device__ __forceinline__ void cp_wait() {
    asm volatile("cp.async.wait_group %0;" :: "n"(N) : "memory");
}
__device__ __forceinline__ uint32_t pack_h2(__half x, __half y) {
    __half2 t; t.x = x; t.y = y;
    return *(uint32_t*)&t;
}

// ---------------- GEMM ----------------
// A smem tile: 128 rows x 128B; units 0-3 = hi (32 fp16), 4-7 = lo (APL=2 only).
// B smem tile: 128 rows x 128B; units 0-3 = data.
// swizzle: unit' = unit ^ (row & 7)
#define KCHUNK 32
#define NITERS (DIM / KCHUNK)
#define TILE_S 16384
#define STAGE_S (2 * TILE_S)
#define NSTAGE 3
#define SMEM_TOTAL (NSTAGE * STAGE_S)   // 98304

// RESID: C += prev C ; WC: write fp32 C ; WSPLIT: write fp16 hi of relu(C)
// WLO: also write lo plane ; APL: A planes (1 = hi only, 2 = hi+lo)
template<int RESID, int WC, int WSPLIT, int WLO, int APL>
__global__ __launch_bounds__(256, 2) void gemm_mma(
    const __half* __restrict__ Ahi, const __half* __restrict__ Alo,
    const __half* __restrict__ Bh,
    const float* __restrict__ bias, float bias_scale,
    float* __restrict__ C,
    __half* __restrict__ Shi, __half* __restrict__ Slo)
{
    extern __shared__ char smem[];
    const uint32_t sb = smem_to_u32(smem);
    const int tid = threadIdx.x;
    const int wid = tid >> 5;
    const int lane = tid & 31;
    const int bx = blockIdx.x, by = blockIdx.y;
    const int wm = wid & 3;
    const int wn = wid >> 2;

    float d[2][8][4];
    #pragma unroll
    for (int i = 0; i < 2; i++)
        #pragma unroll
        for (int j = 0; j < 8; j++)
            #pragma unroll
            for (int q = 0; q < 4; q++) d[i][j][q] = 0.f;

    auto issue = [&](int kc) {
        const int s = kc % NSTAGE;
        const uint32_t stage = sb + s * STAGE_S;
        if (APL == 2) {
            // A hi+lo 1024 units + B 512 units, 6 per thread
            #pragma unroll
            for (int t = 0; t < 6; t++) {
                const int i = tid + t * 256;
                const char* src;
                uint32_t dst;
                if (i < 1024) {
                    const int row = i >> 3;
                    const int unit = i & 7;
                    const __half* plane = (unit < 4) ? Ahi : Alo;
                    src = (const char*)plane + (size_t)(by * 128 + row) * (DIM * 2)
                          + kc * 64 + (unit & 3) * 16;
                    dst = stage + row * 128 + ((unit ^ (row & 7)) << 4);
                } else {
                    const int j = i - 1024;
                    const int row = j >> 2;
                    const int unit = j & 3;
                    src = (const char*)Bh + (size_t)(bx * 128 + row) * (DIM * 2)
                          + kc * 64 + unit * 16;
                    dst = stage + TILE_S + row * 128 + ((unit ^ (row & 7)) << 4);
                }
                cp16(dst, src);
            }
        } else {
            // A hi 512 units + B 512 units, 4 per thread
            #pragma unroll
            for (int t = 0; t < 4; t++) {
                const int i = tid + t * 256;
                const char* src;
                uint32_t dst;
                if (i < 512) {
                    const int row = i >> 2;
                    const int unit = i & 3;
                    src = (const char*)Ahi + (size_t)(by * 128 + row) * (DIM * 2)
                          + kc * 64 + unit * 16;
                    dst = stage + row * 128 + ((unit ^ (row & 7)) << 4);
                } else {
                    const int j = i - 512;
                    const int row = j >> 2;
                    const int unit = j & 3;
                    src = (const char*)Bh + (size_t)(bx * 128 + row) * (DIM * 2)
                          + kc * 64 + unit * 16;
                    dst = stage + TILE_S + row * 128 + ((unit ^ (row & 7)) << 4);
                }
                cp16(dst, src);
            }
        }
        cp_commit();
    };

    issue(0);
    issue(1);

    for (int kc = 0; kc < NITERS; kc++) {
        cp_wait<1>();
        __syncthreads();
        if (kc + 2 < NITERS) issue(kc + 2);

        const uint32_t stage = sb + (kc % NSTAGE) * STAGE_S;
        #pragma unroll
        for (int kh = 0; kh < 2; kh++) {
            uint32_t ah[2][4], al[2][4];
            const int aunit = kh * 2 + (lane >> 4);
            #pragma unroll
            for (int mt = 0; mt < 2; mt++) {
                const int arow = wm * 32 + mt * 16 + (lane & 15);
                const uint32_t hiaddr = stage + arow * 128 + ((aunit ^ (arow & 7)) << 4);
                ldsm4(ah[mt], hiaddr);
                if (APL == 2) ldsm4(al[mt], hiaddr ^ 64);
            }
            const int bunit = kh * 2 + ((lane >> 3) & 1);
            #pragma unroll
            for (int ntp = 0; ntp < 4; ntp++) {
                const int brow = wn * 64 + ntp * 16 + (lane & 7) + (((lane >> 4) & 1) << 3);
                const uint32_t baddr = stage + TILE_S + brow * 128
                                       + ((bunit ^ (brow & 7)) << 4);
                uint32_t bh[4];
                ldsm4(bh, baddr);
                #pragma unroll
                for (int mt = 0; mt < 2; mt++) {
                    #pragma unroll
                    for (int c = 0; c < 2; c++) {
                        float* dd = d[mt][ntp * 2 + c];
                        mma_f16(dd, ah[mt], &bh[2 * c]);
                        if (APL == 2) mma_f16(dd, al[mt], &bh[2 * c]);
                    }
                }
            }
        }
    }

    // ---- epilogue ----
    const int rq = lane >> 2;
    const int cq = (lane & 3) * 2;
    #pragma unroll
    for (int mt = 0; mt < 2; mt++) {
        #pragma unroll
        for (int nt = 0; nt < 8; nt++) {
            const int col = bx * 128 + wn * 64 + nt * 8 + cq;
            const float b0 = bias_scale * bias[col];
            const float b1 = bias_scale * bias[col + 1];
            #pragma unroll
            for (int hrow = 0; hrow < 2; hrow++) {
                const int row = by * 128 + wm * 32 + mt * 16 + rq + hrow * 8;
                float vx = d[mt][nt][hrow * 2 + 0] + b0;
                float vy = d[mt][nt][hrow * 2 + 1] + b1;
                float* cp = C + (size_t)row * DIM + col;
                if (RESID) {
                    float2 old = *(const float2*)cp;
                    vx += old.x; vy += old.y;
                }
                if (WC) *(float2*)cp = make_float2(vx, vy);
                if (WSPLIT) {
                    float rx = fmaxf(vx, 0.f), ry = fmaxf(vy, 0.f);
                    __half hx = __float2half(rx);
                    __half hy = __float2half(ry);
                    const size_t o = (size_t)row * DIM + col;
                    *(uint32_t*)(Shi + o) = pack_h2(hx, hy);
                    if (WLO) {
                        __half lx = __float2half(rx - __half2float(hx));
                        __half ly = __float2half(ry - __half2float(hy));
                        *(uint32_t*)(Slo + o) = pack_h2(lx, ly);
                    }
                }
            }
        }
    }
}

// ---------------- fuse0: split(relu(rep0)+relu(rep1)) -> fp16 hi/lo ----------------
__global__ __launch_bounds__(256) void fuse0(
    const float* __restrict__ rep0, const float* __restrict__ rep1,
    __half* __restrict__ Shi, __half* __restrict__ Slo)
{
    const size_t i = ((size_t)blockIdx.x * blockDim.x + threadIdx.x) * 4;
    float4 a = *(const float4*)(rep0 + i);
    float4 b = *(const float4*)(rep1 + i);
    float v[4] = {fmaxf(a.x, 0.f) + fmaxf(b.x, 0.f),
                  fmaxf(a.y, 0.f) + fmaxf(b.y, 0.f),
                  fmaxf(a.z, 0.f) + fmaxf(b.z, 0.f),
                  fmaxf(a.w, 0.f) + fmaxf(b.w, 0.f)};
    uint32_t hi[2], lo[2];
    #pragma unroll
    for (int q = 0; q < 2; q++) {
        __half hx = __float2half(v[2*q]);
        __half hy = __float2half(v[2*q+1]);
        __half lx = __float2half(v[2*q]   - __half2float(hx));
        __half ly = __float2half(v[2*q+1] - __half2float(hy));
        hi[q] = pack_h2(hx, hy);
        lo[q] = pack_h2(lx, ly);
    }
    *(uint2*)(Shi + i) = make_uint2(hi[0], hi[1]);
    *(uint2*)(Slo + i) = make_uint2(lo[0], lo[1]);
}

// ---------------- weight transpose to fp16 ----------------
__global__ __launch_bounds__(256) void prep_w(const float* __restrict__ W,
                                              __half* __restrict__ Wt)
{
    __shared__ float t[32][33];
    const int n0 = blockIdx.x * 32, k0 = blockIdx.y * 32;
    const int tx = threadIdx.x, ty = threadIdx.y;  // (32, 8)
    #pragma unroll
    for (int i = 0; i < 4; i++)
        t[ty + i * 8][tx] = W[(size_t)(k0 + ty + i * 8) * DIM + n0 + tx];
    __syncthreads();
    #pragma unroll
    for (int i = 0; i < 4; i++)
        Wt[(size_t)(n0 + ty + i * 8) * DIM + k0 + tx] = __float2half(t[tx][ty + i * 8]);
}

// ---------------- torsion head ----------------
__global__ __launch_bounds__(256) void ang_kernel(
    const float* __restrict__ act, const float* __restrict__ w_ang,
    const float* __restrict__ b_ang, float* __restrict__ angbuf)
{
    const int gw = (int)((blockIdx.x * blockDim.x + threadIdx.x) >> 5);
    const int lane = threadIdx.x & 31;
    if (gw >= NROWS) return;
    const float* row = act + (size_t)gw * DIM;
    float acc[14] = {};
    for (int i = lane; i < DIM; i += 32) {
        float a = fmaxf(row[i], 0.f);
        const float* w = w_ang + i * 14;
        #pragma unroll
        for (int j = 0; j < 14; j++) acc[j] = fmaf(a, w[j], acc[j]);
    }
    #pragma unroll
    for (int j = 0; j < 14; j++) {
        #pragma unroll
        for (int off = 16; off; off >>= 1)
            acc[j] += __shfl_down_sync(0xffffffffu, acc[j], off);
    }
    if (lane == 0) {
        float* o = angbuf + (size_t)gw * 14;
        #pragma unroll
        for (int j = 0; j < 14; j++) o[j] = acc[j] + b_ang[j];
    }
}

// ---------------- per-residue geometry ----------------
__global__ __launch_bounds__(128) void epilogue_kernel(
    const float* __restrict__ angbuf,
    const float* __restrict__ rigids, const float* __restrict__ def_frames,
    const float* __restrict__ lit_pos, const float* __restrict__ atom_mask,
    const int* __restrict__ aatype, const int* __restrict__ gidx,
    float* __restrict__ out_angles, float* __restrict__ out_pred,
    float* __restrict__ out_frames)
{
    const int n = blockIdx.x * blockDim.x + threadIdx.x;
    if (n >= NROWS) return;
    const int aa = aatype[n];

    float s[8], c[8];
    s[0] = 0.f; c[0] = 1.f;
    #pragma unroll
    for (int i = 0; i < 7; i++) {
        float ss = angbuf[(size_t)n * 14 + 2 * i];
        float cc = angbuf[(size_t)n * 14 + 2 * i + 1];
        float inv = rsqrtf(fmaxf(ss * ss + cc * cc, 1e-12f));
        ss *= inv; cc *= inv;
        s[i + 1] = ss; c[i + 1] = cc;
        out_angles[(size_t)n * 14 + 2 * i] = ss;
        out_angles[(size_t)n * 14 + 2 * i + 1] = cc;
    }

    float FR[8][9], FT[8][3];
    #pragma unroll
    for (int k = 0; k < 8; k++) {
        const float* D = def_frames + ((size_t)aa * 8 + k) * 16;
        #pragma unroll
        for (int r = 0; r < 3; r++) {
            float d1 = D[r * 4 + 1], d2 = D[r * 4 + 2];
            FR[k][r * 3 + 0] = D[r * 4 + 0];
            FR[k][r * 3 + 1] = c[k] * d1 + s[k] * d2;
            FR[k][r * 3 + 2] = -s[k] * d1 + c[k] * d2;
            FT[k][r] = D[r * 4 + 3];
        }
    }

    #pragma unroll
    for (int k = 5; k <= 7; k++) {
        float R[9], T[3];
        #pragma unroll
        for (int r = 0; r < 3; r++) {
            #pragma unroll
            for (int cc2 = 0; cc2 < 3; cc2++)
                R[r * 3 + cc2] = FR[k - 1][r * 3 + 0] * FR[k][0 + cc2]
                               + FR[k - 1][r * 3 + 1] * FR[k][3 + cc2]
                               + FR[k - 1][r * 3 + 2] * FR[k][6 + cc2];
            T[r] = FR[k - 1][r * 3 + 0] * FT[k][0]
                 + FR[k - 1][r * 3 + 1] * FT[k][1]
                 + FR[k - 1][r * 3 + 2] * FT[k][2] + FT[k - 1][r];
        }
        #pragma unroll
        for (int q = 0; q < 9; q++) FR[k][q] = R[q];
        FT[k][0] = T[0]; FT[k][1] = T[1]; FT[k][2] = T[2];
    }

    const float* rg = rigids + (size_t)n * 16;
    float R0[9] = {rg[0], rg[1], rg[2], rg[4], rg[5], rg[6], rg[8], rg[9], rg[10]};
    float t0[3] = {rg[3], rg[7], rg[11]};

    #pragma unroll
    for (int k = 0; k < 8; k++) {
        float R[9], T[3];
        #pragma unroll
        for (int r = 0; r < 3; r++) {
            #pragma unroll
            for (int cc2 = 0; cc2 < 3; cc2++)
                R[r * 3 + cc2] = R0[r * 3 + 0] * FR[k][0 + cc2]
                               + R0[r * 3 + 1] * FR[k][3 + cc2]
                               + R0[r * 3 + 2] * FR[k][6 + cc2];
            T[r] = R0[r * 3 + 0] * FT[k][0] + R0[r * 3 + 1] * FT[k][1]
                 + R0[r * 3 + 2] * FT[k][2] + t0[r];
        }
        #pragma unroll
        for (int q = 0; q < 9; q++) FR[k][q] = R[q];
        FT[k][0] = T[0]; FT[k][1] = T[1]; FT[k][2] = T[2];

        float* of = out_frames + ((size_t)n * 8 + k) * 16;
        of[0]  = R[0]; of[1]  = R[1]; of[2]  = R[2]; of[3]  = T[0];
        of[4]  = R[3]; of[5]  = R[4]; of[6]  = R[5]; of[7]  = T[1];
        of[8]  = R[6]; of[9]  = R[7]; of[10] = R[8]; of[11] = T[2];
        of[12] = 0.f;  of[13] = 0.f;  of[14] = 0.f;  of[15] = 1.f;
    }

    #pragma unroll
    for (int a = 0; a < 14; a++) {
        int g = gidx[aa * 14 + a];
        const float* p = lit_pos + ((size_t)aa * 14 + a) * 3;
        float m = atom_mask[aa * 14 + a];
        float px = p[0], py = p[1], pz = p[2];
        float* op = out_pred + ((size_t)n * 14 + a) * 3;
        op[0] = (FR[g][0] * px + FR[g][1] * py + FR[g][2] * pz + FT[g][0]) * m;
        op[1] = (FR[g][3] * px + FR[g][4] * py + FR[g][5] * pz + FT[g][1]) * m;
        op[2] = (FR[g][6] * px + FR[g][7] * py + FR[g][8] * pz + FT[g][2]) * m;
    }
}

// ---------------- launch ----------------
extern "C" void kernel_launch(void* const* d_in, const int* in_sizes, int n_in,
                              void* d_out, int out_size)
{
    const float* rep0       = (const float*)d_in[0];
    const float* rep1       = (const float*)d_in[1];
    const float* w_in       = (const float*)d_in[2];
    const float* b_in       = (const float*)d_in[3];
    const float* w1         = (const float*)d_in[4];
    const float* b1         = (const float*)d_in[5];
    const float* w2         = (const float*)d_in[6];
    const float* b2         = (const float*)d_in[7];
    const float* w_ang      = (const float*)d_in[8];
    const float* b_ang      = (const float*)d_in[9];
    const float* rigids     = (const float*)d_in[10];
    const float* def_frames = (const float*)d_in[11];
    const float* lit_pos    = (const float*)d_in[12];
    const float* atom_mask  = (const float*)d_in[13];
    const int*   aatype     = (const int*)d_in[14];
    const int*   gidx       = (const int*)d_in[15];

    float *act, *angb;
    __half *wt, *sah, *sal, *sbh, *sbl;
    cudaGetSymbolAddress((void**)&act, g_act);
    cudaGetSymbolAddress((void**)&angb, g_ang);
    cudaGetSymbolAddress((void**)&wt, g_wt);
    cudaGetSymbolAddress((void**)&sah, g_sa_hi);
    cudaGetSymbolAddress((void**)&sal, g_sa_lo);
    cudaGetSymbolAddress((void**)&sbh, g_sb_hi);
    cudaGetSymbolAddress((void**)&sbl, g_sb_lo);
    const size_t WSZ = (size_t)DIM * DIM;

    cudaFuncSetAttribute(gemm_mma<0,1,1,0,2>, cudaFuncAttributeMaxDynamicSharedMemorySize, SMEM_TOTAL);
    cudaFuncSetAttribute(gemm_mma<0,0,1,1,1>, cudaFuncAttributeMaxDynamicSharedMemorySize, SMEM_TOTAL);
    cudaFuncSetAttribute(gemm_mma<1,1,1,0,2>, cudaFuncAttributeMaxDynamicSharedMemorySize, SMEM_TOTAL);
    cudaFuncSetAttribute(gemm_mma<1,1,0,0,2>, cudaFuncAttributeMaxDynamicSharedMemorySize, SMEM_TOTAL);

    dim3 pg(DIM / 32, DIM / 32), pb(32, 8);
    prep_w<<<pg, pb>>>(w_in, wt + 0 * WSZ);
    prep_w<<<pg, pb>>>(w1,   wt + 1 * WSZ);
    prep_w<<<pg, pb>>>(w2,   wt + 2 * WSZ);

    fuse0<<<(NROWS * DIM) / (256 * 4), 256>>>(rep0, rep1, sah, sal);

    dim3 grid(DIM / 128, NROWS / 128);  // (8, 256)

    // G1 (2-plane): act = in @ w_in^T + 2*b_in ; hi(relu(act)) -> sbh
    gemm_mma<0,1,1,0,2><<<grid, 256, SMEM_TOTAL>>>(sah, sal, wt + 0*WSZ,
                                                   b_in, 2.f, act, sbh, sbl);
    // G2 (1-plane): h = sbh @ w1^T + b1 ; split(relu(h)) -> sa (hi+lo)
    gemm_mma<0,0,1,1,1><<<grid, 256, SMEM_TOTAL>>>(sbh, sbh, wt + 1*WSZ,
                                                   b1, 1.f, act /*unused*/, sah, sal);
    // G3 (2-plane): act += sa @ w2^T + b2 ; hi(relu(act)) -> sbh
    gemm_mma<1,1,1,0,2><<<grid, 256, SMEM_TOTAL>>>(sah, sal, wt + 2*WSZ,
                                                   b2, 1.f, act, sbh, sbl);
    // G4 (1-plane): h = sbh @ w1^T + b1 ; split(relu(h)) -> sa (hi+lo)
    gemm_mma<0,0,1,1,1><<<grid, 256, SMEM_TOTAL>>>(sbh, sbh, wt + 1*WSZ,
                                                   b1, 1.f, act /*unused*/, sah, sal);
    // G5 (2-plane): act += sa @ w2^T + b2
    gemm_mma<1,1,0,0,2><<<grid, 256, SMEM_TOTAL>>>(sah, sal, wt + 2*WSZ,
                                                   b2, 1.f, act, sbh, sbl);

    ang_kernel<<<NROWS / 8, 256>>>(act, w_ang, b_ang, angb);

    float* out = (float*)d_out;
    float* out_angles = out;
    float* out_pred   = out + (size_t)NROWS * 14;
    float* out_frames = out + (size_t)NROWS * 56;
    epilogue_kernel<<<(NROWS + 127) / 128, 128>>>(
        angb, rigids, def_frames, lit_pos, atom_mask, aatype, gidx,
        out_angles, out_pred, out_frames);
}

// round 10
// speedup vs baseline: 5.2421x; 1.1794x over previous
#include <cuda_runtime.h>
#include <cuda_fp16.h>
#include <math.h>
#include <stdint.h>

#define NROWS 32768
#define DIM 1024
#define NRES 21

// ---------------- scratch (no cudaMalloc allowed) ----------------
__device__ float g_act[(size_t)NROWS * DIM];
__device__ float g_ang[(size_t)NROWS * 14];
__device__ __half g_wt[3][(size_t)DIM * DIM];       // transposed fp16 weights [n][k]
__device__ __half g_sa_hi[(size_t)NROWS * DIM];     // activation hi ping
__device__ __half g_sa_lo[(size_t)NROWS * DIM];     // lo plane (G1 input only)
__device__ __half g_sb_hi[(size_t)NROWS * DIM];     // activation hi pong

// ---------------- PTX helpers (baseline compute_103 safe) ----------------
__device__ __forceinline__ uint32_t smem_to_u32(const void* p) {
    uint32_t a;
    asm("{ .reg .u64 t; cvta.to.shared.u64 t, %1; cvt.u32.u64 %0, t; }" : "=r"(a) : "l"(p));
    return a;
}
__device__ __forceinline__ void ldsm4(uint32_t (&r)[4], uint32_t addr) {
    asm volatile("ldmatrix.sync.aligned.m8n8.x4.shared.b16 {%0,%1,%2,%3}, [%4];"
                 : "=r"(r[0]), "=r"(r[1]), "=r"(r[2]), "=r"(r[3]) : "r"(addr));
}
__device__ __forceinline__ void mma_f16(float* d, const uint32_t* a, const uint32_t* b) {
    asm("mma.sync.aligned.m16n8k16.row.col.f32.f16.f16.f32 "
        "{%0,%1,%2,%3}, {%4,%5,%6,%7}, {%8,%9}, {%0,%1,%2,%3};"
        : "+f"(d[0]), "+f"(d[1]), "+f"(d[2]), "+f"(d[3])
        : "r"(a[0]), "r"(a[1]), "r"(a[2]), "r"(a[3]), "r"(b[0]), "r"(b[1]));
}
__device__ __forceinline__ void cp16(uint32_t dst, const void* src) {
    asm volatile("cp.async.cg.shared.global [%0], [%1], 16;" :: "r"(dst), "l"(src));
}
__device__ __forceinline__ void cp_commit() {
    asm volatile("cp.async.commit_group;" ::: "memory");
}
template<int N>
__device__ __forceinline__ void cp_wait() {
    asm volatile("cp.async.wait_group %0;" :: "n"(N) : "memory");
}
__device__ __forceinline__ uint32_t pack_h2(__half x, __half y) {
    __half2 t; t.x = x; t.y = y;
    return *(uint32_t*)&t;
}

// ---------------- GEMM ----------------
// A smem tile: 128 rows x 128B; units 0-3 = hi, 4-7 = lo (APL=2 only).
// B smem tile: 128 rows x 128B; units 0-3 = data.
// swizzle: unit' = unit ^ (row & 7)
#define KCHUNK 32
#define NITERS (DIM / KCHUNK)
#define TILE_S 16384
#define STAGE_S (2 * TILE_S)
#define NSTAGE 3
#define SMEM_TOTAL (NSTAGE * STAGE_S)   // 98304

// RESID: C += prev C ; WC: write fp32 C ; WSPLIT: write fp16 hi of relu(C)
// WLO: also write lo plane ; APL: A planes (1 = hi only, 2 = hi+lo)
template<int RESID, int WC, int WSPLIT, int WLO, int APL>
__global__ __launch_bounds__(256, 2) void gemm_mma(
    const __half* __restrict__ Ahi, const __half* __restrict__ Alo,
    const __half* __restrict__ Bh,
    const float* __restrict__ bias, float bias_scale,
    float* __restrict__ C,
    __half* __restrict__ Shi, __half* __restrict__ Slo)
{
    extern __shared__ char smem[];
    const uint32_t sb = smem_to_u32(smem);
    const int tid = threadIdx.x;
    const int wid = tid >> 5;
    const int lane = tid & 31;
    const int bx = blockIdx.x, by = blockIdx.y;
    const int wm = wid & 3;
    const int wn = wid >> 2;

    float d[2][8][4];
    #pragma unroll
    for (int i = 0; i < 2; i++)
        #pragma unroll
        for (int j = 0; j < 8; j++)
            #pragma unroll
            for (int q = 0; q < 4; q++) d[i][j][q] = 0.f;

    auto issue = [&](int kc) {
        const int s = kc % NSTAGE;
        const uint32_t stage = sb + s * STAGE_S;
        if (APL == 2) {
            #pragma unroll
            for (int t = 0; t < 6; t++) {
                const int i = tid + t * 256;
                const char* src;
                uint32_t dst;
                if (i < 1024) {
                    const int row = i >> 3;
                    const int unit = i & 7;
                    const __half* plane = (unit < 4) ? Ahi : Alo;
                    src = (const char*)plane + (size_t)(by * 128 + row) * (DIM * 2)
                          + kc * 64 + (unit & 3) * 16;
                    dst = stage + row * 128 + ((unit ^ (row & 7)) << 4);
                } else {
                    const int j = i - 1024;
                    const int row = j >> 2;
                    const int unit = j & 3;
                    src = (const char*)Bh + (size_t)(bx * 128 + row) * (DIM * 2)
                          + kc * 64 + unit * 16;
                    dst = stage + TILE_S + row * 128 + ((unit ^ (row & 7)) << 4);
                }
                cp16(dst, src);
            }
        } else {
            #pragma unroll
            for (int t = 0; t < 4; t++) {
                const int i = tid + t * 256;
                const char* src;
                uint32_t dst;
                if (i < 512) {
                    const int row = i >> 2;
                    const int unit = i & 3;
                    src = (const char*)Ahi + (size_t)(by * 128 + row) * (DIM * 2)
                          + kc * 64 + unit * 16;
                    dst = stage + row * 128 + ((unit ^ (row & 7)) << 4);
                } else {
                    const int j = i - 512;
                    const int row = j >> 2;
                    const int unit = j & 3;
                    src = (const char*)Bh + (size_t)(bx * 128 + row) * (DIM * 2)
                          + kc * 64 + unit * 16;
                    dst = stage + TILE_S + row * 128 + ((unit ^ (row & 7)) << 4);
                }
                cp16(dst, src);
            }
        }
        cp_commit();
    };

    issue(0);
    issue(1);

    for (int kc = 0; kc < NITERS; kc++) {
        cp_wait<1>();
        __syncthreads();
        if (kc + 2 < NITERS) issue(kc + 2);

        const uint32_t stage = sb + (kc % NSTAGE) * STAGE_S;
        #pragma unroll
        for (int kh = 0; kh < 2; kh++) {
            uint32_t ah[2][4], al[2][4];
            const int aunit = kh * 2 + (lane >> 4);
            #pragma unroll
            for (int mt = 0; mt < 2; mt++) {
                const int arow = wm * 32 + mt * 16 + (lane & 15);
                const uint32_t hiaddr = stage + arow * 128 + ((aunit ^ (arow & 7)) << 4);
                ldsm4(ah[mt], hiaddr);
                if (APL == 2) ldsm4(al[mt], hiaddr ^ 64);
            }
            const int bunit = kh * 2 + ((lane >> 3) & 1);
            #pragma unroll
            for (int ntp = 0; ntp < 4; ntp++) {
                const int brow = wn * 64 + ntp * 16 + (lane & 7) + (((lane >> 4) & 1) << 3);
                const uint32_t baddr = stage + TILE_S + brow * 128
                                       + ((bunit ^ (brow & 7)) << 4);
                uint32_t bh[4];
                ldsm4(bh, baddr);
                #pragma unroll
                for (int mt = 0; mt < 2; mt++) {
                    #pragma unroll
                    for (int c = 0; c < 2; c++) {
                        float* dd = d[mt][ntp * 2 + c];
                        mma_f16(dd, ah[mt], &bh[2 * c]);
                        if (APL == 2) mma_f16(dd, al[mt], &bh[2 * c]);
                    }
                }
            }
        }
    }

    // ---- epilogue ----
    const int rq = lane >> 2;
    const int cq = (lane & 3) * 2;
    #pragma unroll
    for (int mt = 0; mt < 2; mt++) {
        #pragma unroll
        for (int nt = 0; nt < 8; nt++) {
            const int col = bx * 128 + wn * 64 + nt * 8 + cq;
            const float b0 = bias_scale * bias[col];
            const float b1 = bias_scale * bias[col + 1];
            #pragma unroll
            for (int hrow = 0; hrow < 2; hrow++) {
                const int row = by * 128 + wm * 32 + mt * 16 + rq + hrow * 8;
                float vx = d[mt][nt][hrow * 2 + 0] + b0;
                float vy = d[mt][nt][hrow * 2 + 1] + b1;
                float* cp = C + (size_t)row * DIM + col;
                if (RESID) {
                    float2 old = *(const float2*)cp;
                    vx += old.x; vy += old.y;
                }
                if (WC) *(float2*)cp = make_float2(vx, vy);
                if (WSPLIT) {
                    float rx = fmaxf(vx, 0.f), ry = fmaxf(vy, 0.f);
                    __half hx = __float2half(rx);
                    __half hy = __float2half(ry);
                    const size_t o = (size_t)row * DIM + col;
                    *(uint32_t*)(Shi + o) = pack_h2(hx, hy);
                    if (WLO) {
                        __half lx = __float2half(rx - __half2float(hx));
                        __half ly = __float2half(ry - __half2float(hy));
                        *(uint32_t*)(Slo + o) = pack_h2(lx, ly);
                    }
                }
            }
        }
    }
}

// ---------------- fuse0: split(relu(rep0)+relu(rep1)) -> fp16 hi/lo ----------------
__global__ __launch_bounds__(256) void fuse0(
    const float* __restrict__ rep0, const float* __restrict__ rep1,
    __half* __restrict__ Shi, __half* __restrict__ Slo)
{
    const size_t i = ((size_t)blockIdx.x * blockDim.x + threadIdx.x) * 4;
    float4 a = *(const float4*)(rep0 + i);
    float4 b = *(const float4*)(rep1 + i);
    float v[4] = {fmaxf(a.x, 0.f) + fmaxf(b.x, 0.f),
                  fmaxf(a.y, 0.f) + fmaxf(b.y, 0.f),
                  fmaxf(a.z, 0.f) + fmaxf(b.z, 0.f),
                  fmaxf(a.w, 0.f) + fmaxf(b.w, 0.f)};
    uint32_t hi[2], lo[2];
    #pragma unroll
    for (int q = 0; q < 2; q++) {
        __half hx = __float2half(v[2*q]);
        __half hy = __float2half(v[2*q+1]);
        __half lx = __float2half(v[2*q]   - __half2float(hx));
        __half ly = __float2half(v[2*q+1] - __half2float(hy));
        hi[q] = pack_h2(hx, hy);
        lo[q] = pack_h2(lx, ly);
    }
    *(uint2*)(Shi + i) = make_uint2(hi[0], hi[1]);
    *(uint2*)(Slo + i) = make_uint2(lo[0], lo[1]);
}

// ---------------- weight transpose to fp16 ----------------
__global__ __launch_bounds__(256) void prep_w(const float* __restrict__ W,
                                              __half* __restrict__ Wt)
{
    __shared__ float t[32][33];
    const int n0 = blockIdx.x * 32, k0 = blockIdx.y * 32;
    const int tx = threadIdx.x, ty = threadIdx.y;  // (32, 8)
    #pragma unroll
    for (int i = 0; i < 4; i++)
        t[ty + i * 8][tx] = W[(size_t)(k0 + ty + i * 8) * DIM + n0 + tx];
    __syncthreads();
    #pragma unroll
    for (int i = 0; i < 4; i++)
        Wt[(size_t)(n0 + ty + i * 8) * DIM + k0 + tx] = __float2half(t[tx][ty + i * 8]);
}

// ---------------- torsion head ----------------
__global__ __launch_bounds__(256) void ang_kernel(
    const float* __restrict__ act, const float* __restrict__ w_ang,
    const float* __restrict__ b_ang, float* __restrict__ angbuf)
{
    const int gw = (int)((blockIdx.x * blockDim.x + threadIdx.x) >> 5);
    const int lane = threadIdx.x & 31;
    if (gw >= NROWS) return;
    const float* row = act + (size_t)gw * DIM;
    float acc[14] = {};
    for (int i = lane; i < DIM; i += 32) {
        float a = fmaxf(row[i], 0.f);
        const float* w = w_ang + i * 14;
        #pragma unroll
        for (int j = 0; j < 14; j++) acc[j] = fmaf(a, w[j], acc[j]);
    }
    #pragma unroll
    for (int j = 0; j < 14; j++) {
        #pragma unroll
        for (int off = 16; off; off >>= 1)
            acc[j] += __shfl_down_sync(0xffffffffu, acc[j], off);
    }
    if (lane == 0) {
        float* o = angbuf + (size_t)gw * 14;
        #pragma unroll
        for (int j = 0; j < 14; j++) o[j] = acc[j] + b_ang[j];
    }
}

// ---------------- per-residue geometry ----------------
__global__ __launch_bounds__(128) void epilogue_kernel(
    const float* __restrict__ angbuf,
    const float* __restrict__ rigids, const float* __restrict__ def_frames,
    const float* __restrict__ lit_pos, const float* __restrict__ atom_mask,
    const int* __restrict__ aatype, const int* __restrict__ gidx,
    float* __restrict__ out_angles, float* __restrict__ out_pred,
    float* __restrict__ out_frames)
{
    const int n = blockIdx.x * blockDim.x + threadIdx.x;
    if (n >= NROWS) return;
    const int aa = aatype[n];

    float s[8], c[8];
    s[0] = 0.f; c[0] = 1.f;
    #pragma unroll
    for (int i = 0; i < 7; i++) {
        float ss = angbuf[(size_t)n * 14 + 2 * i];
        float cc = angbuf[(size_t)n * 14 + 2 * i + 1];
        float inv = rsqrtf(fmaxf(ss * ss + cc * cc, 1e-12f));
        ss *= inv; cc *= inv;
        s[i + 1] = ss; c[i + 1] = cc;
        out_angles[(size_t)n * 14 + 2 * i] = ss;
        out_angles[(size_t)n * 14 + 2 * i + 1] = cc;
    }

    float FR[8][9], FT[8][3];
    #pragma unroll
    for (int k = 0; k < 8; k++) {
        const float* D = def_frames + ((size_t)aa * 8 + k) * 16;
        #pragma unroll
        for (int r = 0; r < 3; r++) {
            float d1 = D[r * 4 + 1], d2 = D[r * 4 + 2];
            FR[k][r * 3 + 0] = D[r * 4 + 0];
            FR[k][r * 3 + 1] = c[k] * d1 + s[k] * d2;
            FR[k][r * 3 + 2] = -s[k] * d1 + c[k] * d2;
            FT[k][r] = D[r * 4 + 3];
        }
    }

    #pragma unroll
    for (int k = 5; k <= 7; k++) {
        float R[9], T[3];
        #pragma unroll
        for (int r = 0; r < 3; r++) {
            #pragma unroll
            for (int cc2 = 0; cc2 < 3; cc2++)
                R[r * 3 + cc2] = FR[k - 1][r * 3 + 0] * FR[k][0 + cc2]
                               + FR[k - 1][r * 3 + 1] * FR[k][3 + cc2]
                               + FR[k - 1][r * 3 + 2] * FR[k][6 + cc2];
            T[r] = FR[k - 1][r * 3 + 0] * FT[k][0]
                 + FR[k - 1][r * 3 + 1] * FT[k][1]
                 + FR[k - 1][r * 3 + 2] * FT[k][2] + FT[k - 1][r];
        }
        #pragma unroll
        for (int q = 0; q < 9; q++) FR[k][q] = R[q];
        FT[k][0] = T[0]; FT[k][1] = T[1]; FT[k][2] = T[2];
    }

    const float* rg = rigids + (size_t)n * 16;
    float R0[9] = {rg[0], rg[1], rg[2], rg[4], rg[5], rg[6], rg[8], rg[9], rg[10]};
    float t0[3] = {rg[3], rg[7], rg[11]};

    #pragma unroll
    for (int k = 0; k < 8; k++) {
        float R[9], T[3];
        #pragma unroll
        for (int r = 0; r < 3; r++) {
            #pragma unroll
            for (int cc2 = 0; cc2 < 3; cc2++)
                R[r * 3 + cc2] = R0[r * 3 + 0] * FR[k][0 + cc2]
                               + R0[r * 3 + 1] * FR[k][3 + cc2]
                               + R0[r * 3 + 2] * FR[k][6 + cc2];
            T[r] = R0[r * 3 + 0] * FT[k][0] + R0[r * 3 + 1] * FT[k][1]
                 + R0[r * 3 + 2] * FT[k][2] + t0[r];
        }
        #pragma unroll
        for (int q = 0; q < 9; q++) FR[k][q] = R[q];
        FT[k][0] = T[0]; FT[k][1] = T[1]; FT[k][2] = T[2];

        float* of = out_frames + ((size_t)n * 8 + k) * 16;
        of[0]  = R[0]; of[1]  = R[1]; of[2]  = R[2]; of[3]  = T[0];
        of[4]  = R[3]; of[5]  = R[4]; of[6]  = R[5]; of[7]  = T[1];
        of[8]  = R[6]; of[9]  = R[7]; of[10] = R[8]; of[11] = T[2];
        of[12] = 0.f;  of[13] = 0.f;  of[14] = 0.f;  of[15] = 1.f;
    }

    #pragma unroll
    for (int a = 0; a < 14; a++) {
        int g = gidx[aa * 14 + a];
        const float* p = lit_pos + ((size_t)aa * 14 + a) * 3;
        float m = atom_mask[aa * 14 + a];
        float px = p[0], py = p[1], pz = p[2];
        float* op = out_pred + ((size_t)n * 14 + a) * 3;
        op[0] = (FR[g][0] * px + FR[g][1] * py + FR[g][2] * pz + FT[g][0]) * m;
        op[1] = (FR[g][3] * px + FR[g][4] * py + FR[g][5] * pz + FT[g][1]) * m;
        op[2] = (FR[g][6] * px + FR[g][7] * py + FR[g][8] * pz + FT[g][2]) * m;
    }
}

// ---------------- launch ----------------
extern "C" void kernel_launch(void* const* d_in, const int* in_sizes, int n_in,
                              void* d_out, int out_size)
{
    const float* rep0       = (const float*)d_in[0];
    const float* rep1       = (const float*)d_in[1];
    const float* w_in       = (const float*)d_in[2];
    const float* b_in       = (const float*)d_in[3];
    const float* w1         = (const float*)d_in[4];
    const float* b1         = (const float*)d_in[5];
    const float* w2         = (const float*)d_in[6];
    const float* b2         = (const float*)d_in[7];
    const float* w_ang      = (const float*)d_in[8];
    const float* b_ang      = (const float*)d_in[9];
    const float* rigids     = (const float*)d_in[10];
    const float* def_frames = (const float*)d_in[11];
    const float* lit_pos    = (const float*)d_in[12];
    const float* atom_mask  = (const float*)d_in[13];
    const int*   aatype     = (const int*)d_in[14];
    const int*   gidx       = (const int*)d_in[15];

    float *act, *angb;
    __half *wt, *sah, *sal, *sbh;
    cudaGetSymbolAddress((void**)&act, g_act);
    cudaGetSymbolAddress((void**)&angb, g_ang);
    cudaGetSymbolAddress((void**)&wt, g_wt);
    cudaGetSymbolAddress((void**)&sah, g_sa_hi);
    cudaGetSymbolAddress((void**)&sal, g_sa_lo);
    cudaGetSymbolAddress((void**)&sbh, g_sb_hi);
    const size_t WSZ = (size_t)DIM * DIM;

    cudaFuncSetAttribute(gemm_mma<0,1,1,0,2>, cudaFuncAttributeMaxDynamicSharedMemorySize, SMEM_TOTAL);
    cudaFuncSetAttribute(gemm_mma<0,0,1,0,1>, cudaFuncAttributeMaxDynamicSharedMemorySize, SMEM_TOTAL);
    cudaFuncSetAttribute(gemm_mma<1,1,1,0,1>, cudaFuncAttributeMaxDynamicSharedMemorySize, SMEM_TOTAL);
    cudaFuncSetAttribute(gemm_mma<1,1,0,0,1>, cudaFuncAttributeMaxDynamicSharedMemorySize, SMEM_TOTAL);

    dim3 pg(DIM / 32, DIM / 32), pb(32, 8);
    prep_w<<<pg, pb>>>(w_in, wt + 0 * WSZ);
    prep_w<<<pg, pb>>>(w1,   wt + 1 * WSZ);
    prep_w<<<pg, pb>>>(w2,   wt + 2 * WSZ);

    fuse0<<<(NROWS * DIM) / (256 * 4), 256>>>(rep0, rep1, sah, sal);

    dim3 grid(DIM / 128, NROWS / 128);  // (8, 256)

    // G1 (2-plane A): act = in @ w_in^T + 2*b_in ; hi(relu(act)) -> sbh
    gemm_mma<0,1,1,0,2><<<grid, 256, SMEM_TOTAL>>>(sah, sal, wt + 0*WSZ,
                                                   b_in, 2.f, act, sbh, nullptr);
    // G2 (1-plane): h = sbh @ w1^T + b1 ; hi(relu(h)) -> sah
    gemm_mma<0,0,1,0,1><<<grid, 256, SMEM_TOTAL>>>(sbh, sbh, wt + 1*WSZ,
                                                   b1, 1.f, act /*unused*/, sah, nullptr);
    // G3 (1-plane): act += sah @ w2^T + b2 ; hi(relu(act)) -> sbh
    gemm_mma<1,1,1,0,1><<<grid, 256, SMEM_TOTAL>>>(sah, sah, wt + 2*WSZ,
                                                   b2, 1.f, act, sbh, nullptr);
    // G4 (1-plane): h = sbh @ w1^T + b1 ; hi(relu(h)) -> sah
    gemm_mma<0,0,1,0,1><<<grid, 256, SMEM_TOTAL>>>(sbh, sbh, wt + 1*WSZ,
                                                   b1, 1.f, act /*unused*/, sah, nullptr);
    // G5 (1-plane): act += sah @ w2^T + b2
    gemm_mma<1,1,0,0,1><<<grid, 256, SMEM_TOTAL>>>(sah, sah, wt + 2*WSZ,
                                                   b2, 1.f, act, sbh, nullptr);

    ang_kernel<<<NROWS / 8, 256>>>(act, w_ang, b_ang, angb);

    float* out = (float*)d_out;
    float* out_angles = out;
    float* out_pred   = out + (size_t)NROWS * 14;
    float* out_frames = out + (size_t)NROWS * 56;
    epilogue_kernel<<<(NROWS + 127) / 128, 128>>>(
        angb, rigids, def_frames, lit_pos, atom_mask, aatype, gidx,
        out_angles, out_pred, out_frames);
}

// round 11
// speedup vs baseline: 5.7815x; 1.1029x over previous
#include <cuda_runtime.h>
#include <cuda_fp16.h>
#include <math.h>
#include <stdint.h>

#define NROWS 32768
#define DIM 1024
#define NRES 21

// ---------------- scratch (no cudaMalloc allowed) ----------------
__device__ float g_act[(size_t)NROWS * DIM];
__device__ float g_ang[(size_t)NROWS * 14];
__device__ __half g_wt[3][(size_t)DIM * DIM];       // transposed fp16 weights [n][k]
__device__ __half g_sa_hi[(size_t)NROWS * DIM];     // activation hi ping
__device__ __half g_sb_hi[(size_t)NROWS * DIM];     // activation hi pong

// ---------------- PTX helpers (baseline compute_103 safe) ----------------
__device__ __forceinline__ uint32_t smem_to_u32(const void* p) {
    uint32_t a;
    asm("{ .reg .u64 t; cvta.to.shared.u64 t, %1; cvt.u32.u64 %0, t; }" : "=r"(a) : "l"(p));
    return a;
}
__device__ __forceinline__ void ldsm4(uint32_t (&r)[4], uint32_t addr) {
    asm volatile("ldmatrix.sync.aligned.m8n8.x4.shared.b16 {%0,%1,%2,%3}, [%4];"
                 : "=r"(r[0]), "=r"(r[1]), "=r"(r[2]), "=r"(r[3]) : "r"(addr));
}
__device__ __forceinline__ void mma_f16(float* d, const uint32_t* a, const uint32_t* b) {
    asm("mma.sync.aligned.m16n8k16.row.col.f32.f16.f16.f32 "
        "{%0,%1,%2,%3}, {%4,%5,%6,%7}, {%8,%9}, {%0,%1,%2,%3};"
        : "+f"(d[0]), "+f"(d[1]), "+f"(d[2]), "+f"(d[3])
        : "r"(a[0]), "r"(a[1]), "r"(a[2]), "r"(a[3]), "r"(b[0]), "r"(b[1]));
}
__device__ __forceinline__ void cp16(uint32_t dst, const void* src) {
    asm volatile("cp.async.cg.shared.global [%0], [%1], 16;" :: "r"(dst), "l"(src));
}
__device__ __forceinline__ void cp_commit() {
    asm volatile("cp.async.commit_group;" ::: "memory");
}
template<int N>
__device__ __forceinline__ void cp_wait() {
    asm volatile("cp.async.wait_group %0;" :: "n"(N) : "memory");
}
__device__ __forceinline__ uint32_t pack_h2(__half x, __half y) {
    __half2 t; t.x = x; t.y = y;
    return *(uint32_t*)&t;
}

// ---------------- GEMM (all single-plane fp16) ----------------
// A smem tile: 128 rows x 128B; units 0-3 = data (32 fp16), 4-7 unused.
// B smem tile: same.  swizzle: unit' = unit ^ (row & 7)
#define KCHUNK 32
#define NITERS (DIM / KCHUNK)
#define TILE_S 16384
#define STAGE_S (2 * TILE_S)
#define NSTAGE 3
#define SMEM_TOTAL (NSTAGE * STAGE_S)   // 98304

// RESID: C += prev C ; WC: write fp32 C ; WSPLIT: write fp16 hi of relu(C)
template<int RESID, int WC, int WSPLIT>
__global__ __launch_bounds__(256, 2) void gemm_mma(
    const __half* __restrict__ Ah, const __half* __restrict__ Bh,
    const float* __restrict__ bias, float bias_scale,
    float* __restrict__ C, __half* __restrict__ Shi)
{
    extern __shared__ char smem[];
    const uint32_t sb = smem_to_u32(smem);
    const int tid = threadIdx.x;
    const int wid = tid >> 5;
    const int lane = tid & 31;
    const int bx = blockIdx.x, by = blockIdx.y;
    const int wm = wid & 3;
    const int wn = wid >> 2;

    float d[2][8][4];
    #pragma unroll
    for (int i = 0; i < 2; i++)
        #pragma unroll
        for (int j = 0; j < 8; j++)
            #pragma unroll
            for (int q = 0; q < 4; q++) d[i][j][q] = 0.f;

    auto issue = [&](int kc) {
        const int s = kc % NSTAGE;
        const uint32_t stage = sb + s * STAGE_S;
        #pragma unroll
        for (int t = 0; t < 4; t++) {
            const int i = tid + t * 256;
            const char* src;
            uint32_t dst;
            if (i < 512) {
                const int row = i >> 2;
                const int unit = i & 3;
                src = (const char*)Ah + (size_t)(by * 128 + row) * (DIM * 2)
                      + kc * 64 + unit * 16;
                dst = stage + row * 128 + ((unit ^ (row & 7)) << 4);
            } else {
                const int j = i - 512;
                const int row = j >> 2;
                const int unit = j & 3;
                src = (const char*)Bh + (size_t)(bx * 128 + row) * (DIM * 2)
                      + kc * 64 + unit * 16;
                dst = stage + TILE_S + row * 128 + ((unit ^ (row & 7)) << 4);
            }
            cp16(dst, src);
        }
        cp_commit();
    };

    issue(0);
    issue(1);

    for (int kc = 0; kc < NITERS; kc++) {
        cp_wait<1>();
        __syncthreads();
        if (kc + 2 < NITERS) issue(kc + 2);

        const uint32_t stage = sb + (kc % NSTAGE) * STAGE_S;
        #pragma unroll
        for (int kh = 0; kh < 2; kh++) {
            uint32_t ah[2][4];
            const int aunit = kh * 2 + (lane >> 4);
            #pragma unroll
            for (int mt = 0; mt < 2; mt++) {
                const int arow = wm * 32 + mt * 16 + (lane & 15);
                ldsm4(ah[mt], stage + arow * 128 + ((aunit ^ (arow & 7)) << 4));
            }
            const int bunit = kh * 2 + ((lane >> 3) & 1);
            #pragma unroll
            for (int ntp = 0; ntp < 4; ntp++) {
                const int brow = wn * 64 + ntp * 16 + (lane & 7) + (((lane >> 4) & 1) << 3);
                uint32_t bh[4];
                ldsm4(bh, stage + TILE_S + brow * 128 + ((bunit ^ (brow & 7)) << 4));
                #pragma unroll
                for (int mt = 0; mt < 2; mt++) {
                    #pragma unroll
                    for (int c = 0; c < 2; c++)
                        mma_f16(d[mt][ntp * 2 + c], ah[mt], &bh[2 * c]);
                }
            }
        }
    }

    // ---- epilogue ----
    const int rq = lane >> 2;
    const int cq = (lane & 3) * 2;
    #pragma unroll
    for (int mt = 0; mt < 2; mt++) {
        #pragma unroll
        for (int nt = 0; nt < 8; nt++) {
            const int col = bx * 128 + wn * 64 + nt * 8 + cq;
            const float b0 = bias_scale * bias[col];
            const float b1 = bias_scale * bias[col + 1];
            #pragma unroll
            for (int hrow = 0; hrow < 2; hrow++) {
                const int row = by * 128 + wm * 32 + mt * 16 + rq + hrow * 8;
                float vx = d[mt][nt][hrow * 2 + 0] + b0;
                float vy = d[mt][nt][hrow * 2 + 1] + b1;
                float* cp = C + (size_t)row * DIM + col;
                if (RESID) {
                    float2 old = *(const float2*)cp;
                    vx += old.x; vy += old.y;
                }
                if (WC) *(float2*)cp = make_float2(vx, vy);
                if (WSPLIT) {
                    const size_t o = (size_t)row * DIM + col;
                    *(uint32_t*)(Shi + o) = pack_h2(__float2half(fmaxf(vx, 0.f)),
                                                    __float2half(fmaxf(vy, 0.f)));
                }
            }
        }
    }
}

// ---------------- fuse0: fp16(relu(rep0)+relu(rep1)) ----------------
__global__ __launch_bounds__(256) void fuse0(
    const float* __restrict__ rep0, const float* __restrict__ rep1,
    __half* __restrict__ Shi)
{
    const size_t i = ((size_t)blockIdx.x * blockDim.x + threadIdx.x) * 4;
    float4 a = *(const float4*)(rep0 + i);
    float4 b = *(const float4*)(rep1 + i);
    float v0 = fmaxf(a.x, 0.f) + fmaxf(b.x, 0.f);
    float v1 = fmaxf(a.y, 0.f) + fmaxf(b.y, 0.f);
    float v2 = fmaxf(a.z, 0.f) + fmaxf(b.z, 0.f);
    float v3 = fmaxf(a.w, 0.f) + fmaxf(b.w, 0.f);
    uint2 o;
    o.x = pack_h2(__float2half(v0), __float2half(v1));
    o.y = pack_h2(__float2half(v2), __float2half(v3));
    *(uint2*)(Shi + i) = o;
}

// ---------------- weight transpose to fp16 ----------------
__global__ __launch_bounds__(256) void prep_w(const float* __restrict__ W,
                                              __half* __restrict__ Wt)
{
    __shared__ float t[32][33];
    const int n0 = blockIdx.x * 32, k0 = blockIdx.y * 32;
    const int tx = threadIdx.x, ty = threadIdx.y;  // (32, 8)
    #pragma unroll
    for (int i = 0; i < 4; i++)
        t[ty + i * 8][tx] = W[(size_t)(k0 + ty + i * 8) * DIM + n0 + tx];
    __syncthreads();
    #pragma unroll
    for (int i = 0; i < 4; i++)
        Wt[(size_t)(n0 + ty + i * 8) * DIM + k0 + tx] = __float2half(t[tx][ty + i * 8]);
}

// ---------------- torsion head ----------------
__global__ __launch_bounds__(256) void ang_kernel(
    const float* __restrict__ act, const float* __restrict__ w_ang,
    const float* __restrict__ b_ang, float* __restrict__ angbuf)
{
    const int gw = (int)((blockIdx.x * blockDim.x + threadIdx.x) >> 5);
    const int lane = threadIdx.x & 31;
    if (gw >= NROWS) return;
    const float* row = act + (size_t)gw * DIM;
    float acc[14] = {};
    for (int i = lane; i < DIM; i += 32) {
        float a = fmaxf(row[i], 0.f);
        const float* w = w_ang + i * 14;
        #pragma unroll
        for (int j = 0; j < 14; j++) acc[j] = fmaf(a, w[j], acc[j]);
    }
    #pragma unroll
    for (int j = 0; j < 14; j++) {
        #pragma unroll
        for (int off = 16; off; off >>= 1)
            acc[j] += __shfl_down_sync(0xffffffffu, acc[j], off);
    }
    if (lane == 0) {
        float* o = angbuf + (size_t)gw * 14;
        #pragma unroll
        for (int j = 0; j < 14; j++) o[j] = acc[j] + b_ang[j];
    }
}

// ---------------- per-residue geometry ----------------
__global__ __launch_bounds__(128) void epilogue_kernel(
    const float* __restrict__ angbuf,
    const float* __restrict__ rigids, const float* __restrict__ def_frames,
    const float* __restrict__ lit_pos, const float* __restrict__ atom_mask,
    const int* __restrict__ aatype, const int* __restrict__ gidx,
    float* __restrict__ out_angles, float* __restrict__ out_pred,
    float* __restrict__ out_frames)
{
    const int n = blockIdx.x * blockDim.x + threadIdx.x;
    if (n >= NROWS) return;
    const int aa = aatype[n];

    float s[8], c[8];
    s[0] = 0.f; c[0] = 1.f;
    #pragma unroll
    for (int i = 0; i < 7; i++) {
        float ss = angbuf[(size_t)n * 14 + 2 * i];
        float cc = angbuf[(size_t)n * 14 + 2 * i + 1];
        float inv = rsqrtf(fmaxf(ss * ss + cc * cc, 1e-12f));
        ss *= inv; cc *= inv;
        s[i + 1] = ss; c[i + 1] = cc;
        out_angles[(size_t)n * 14 + 2 * i] = ss;
        out_angles[(size_t)n * 14 + 2 * i + 1] = cc;
    }

    float FR[8][9], FT[8][3];
    #pragma unroll
    for (int k = 0; k < 8; k++) {
        const float* D = def_frames + ((size_t)aa * 8 + k) * 16;
        #pragma unroll
        for (int r = 0; r < 3; r++) {
            float d1 = D[r * 4 + 1], d2 = D[r * 4 + 2];
            FR[k][r * 3 + 0] = D[r * 4 + 0];
            FR[k][r * 3 + 1] = c[k] * d1 + s[k] * d2;
            FR[k][r * 3 + 2] = -s[k] * d1 + c[k] * d2;
            FT[k][r] = D[r * 4 + 3];
        }
    }

    #pragma unroll
    for (int k = 5; k <= 7; k++) {
        float R[9], T[3];
        #pragma unroll
        for (int r = 0; r < 3; r++) {
            #pragma unroll
            for (int cc2 = 0; cc2 < 3; cc2++)
                R[r * 3 + cc2] = FR[k - 1][r * 3 + 0] * FR[k][0 + cc2]
                               + FR[k - 1][r * 3 + 1] * FR[k][3 + cc2]
                               + FR[k - 1][r * 3 + 2] * FR[k][6 + cc2];
            T[r] = FR[k - 1][r * 3 + 0] * FT[k][0]
                 + FR[k - 1][r * 3 + 1] * FT[k][1]
                 + FR[k - 1][r * 3 + 2] * FT[k][2] + FT[k - 1][r];
        }
        #pragma unroll
        for (int q = 0; q < 9; q++) FR[k][q] = R[q];
        FT[k][0] = T[0]; FT[k][1] = T[1]; FT[k][2] = T[2];
    }

    const float* rg = rigids + (size_t)n * 16;
    float R0[9] = {rg[0], rg[1], rg[2], rg[4], rg[5], rg[6], rg[8], rg[9], rg[10]};
    float t0[3] = {rg[3], rg[7], rg[11]};

    #pragma unroll
    for (int k = 0; k < 8; k++) {
        float R[9], T[3];
        #pragma unroll
        for (int r = 0; r < 3; r++) {
            #pragma unroll
            for (int cc2 = 0; cc2 < 3; cc2++)
                R[r * 3 + cc2] = R0[r * 3 + 0] * FR[k][0 + cc2]
                               + R0[r * 3 + 1] * FR[k][3 + cc2]
                               + R0[r * 3 + 2] * FR[k][6 + cc2];
            T[r] = R0[r * 3 + 0] * FT[k][0] + R0[r * 3 + 1] * FT[k][1]
                 + R0[r * 3 + 2] * FT[k][2] + t0[r];
        }
        #pragma unroll
        for (int q = 0; q < 9; q++) FR[k][q] = R[q];
        FT[k][0] = T[0]; FT[k][1] = T[1]; FT[k][2] = T[2];

        float* of = out_frames + ((size_t)n * 8 + k) * 16;
        of[0]  = R[0]; of[1]  = R[1]; of[2]  = R[2]; of[3]  = T[0];
        of[4]  = R[3]; of[5]  = R[4]; of[6]  = R[5]; of[7]  = T[1];
        of[8]  = R[6]; of[9]  = R[7]; of[10] = R[8]; of[11] = T[2];
        of[12] = 0.f;  of[13] = 0.f;  of[14] = 0.f;  of[15] = 1.f;
    }

    #pragma unroll
    for (int a = 0; a < 14; a++) {
        int g = gidx[aa * 14 + a];
        const float* p = lit_pos + ((size_t)aa * 14 + a) * 3;
        float m = atom_mask[aa * 14 + a];
        float px = p[0], py = p[1], pz = p[2];
        float* op = out_pred + ((size_t)n * 14 + a) * 3;
        op[0] = (FR[g][0] * px + FR[g][1] * py + FR[g][2] * pz + FT[g][0]) * m;
        op[1] = (FR[g][3] * px + FR[g][4] * py + FR[g][5] * pz + FT[g][1]) * m;
        op[2] = (FR[g][6] * px + FR[g][7] * py + FR[g][8] * pz + FT[g][2]) * m;
    }
}

// ---------------- launch ----------------
extern "C" void kernel_launch(void* const* d_in, const int* in_sizes, int n_in,
                              void* d_out, int out_size)
{
    const float* rep0       = (const float*)d_in[0];
    const float* rep1       = (const float*)d_in[1];
    const float* w_in       = (const float*)d_in[2];
    const float* b_in       = (const float*)d_in[3];
    const float* w1         = (const float*)d_in[4];
    const float* b1         = (const float*)d_in[5];
    const float* w2         = (const float*)d_in[6];
    const float* b2         = (const float*)d_in[7];
    const float* w_ang      = (const float*)d_in[8];
    const float* b_ang      = (const float*)d_in[9];
    const float* rigids     = (const float*)d_in[10];
    const float* def_frames = (const float*)d_in[11];
    const float* lit_pos    = (const float*)d_in[12];
    const float* atom_mask  = (const float*)d_in[13];
    const int*   aatype     = (const int*)d_in[14];
    const int*   gidx       = (const int*)d_in[15];

    float *act, *angb;
    __half *wt, *sah, *sbh;
    cudaGetSymbolAddress((void**)&act, g_act);
    cudaGetSymbolAddress((void**)&angb, g_ang);
    cudaGetSymbolAddress((void**)&wt, g_wt);
    cudaGetSymbolAddress((void**)&sah, g_sa_hi);
    cudaGetSymbolAddress((void**)&sbh, g_sb_hi);
    const size_t WSZ = (size_t)DIM * DIM;

    cudaFuncSetAttribute(gemm_mma<0,1,1>, cudaFuncAttributeMaxDynamicSharedMemorySize, SMEM_TOTAL);
    cudaFuncSetAttribute(gemm_mma<0,0,1>, cudaFuncAttributeMaxDynamicSharedMemorySize, SMEM_TOTAL);
    cudaFuncSetAttribute(gemm_mma<1,1,1>, cudaFuncAttributeMaxDynamicSharedMemorySize, SMEM_TOTAL);
    cudaFuncSetAttribute(gemm_mma<1,1,0>, cudaFuncAttributeMaxDynamicSharedMemorySize, SMEM_TOTAL);

    dim3 pg(DIM / 32, DIM / 32), pb(32, 8);
    prep_w<<<pg, pb>>>(w_in, wt + 0 * WSZ);
    prep_w<<<pg, pb>>>(w1,   wt + 1 * WSZ);
    prep_w<<<pg, pb>>>(w2,   wt + 2 * WSZ);

    fuse0<<<(NROWS * DIM) / (256 * 4), 256>>>(rep0, rep1, sah);

    dim3 grid(DIM / 128, NROWS / 128);  // (8, 256)

    // G1: act = sah @ w_in^T + 2*b_in ; hi(relu(act)) -> sbh
    gemm_mma<0,1,1><<<grid, 256, SMEM_TOTAL>>>(sah, wt + 0*WSZ, b_in, 2.f, act, sbh);
    // G2: h = sbh @ w1^T + b1 ; hi(relu(h)) -> sah
    gemm_mma<0,0,1><<<grid, 256, SMEM_TOTAL>>>(sbh, wt + 1*WSZ, b1, 1.f, act, sah);
    // G3: act += sah @ w2^T + b2 ; hi(relu(act)) -> sbh
    gemm_mma<1,1,1><<<grid, 256, SMEM_TOTAL>>>(sah, wt + 2*WSZ, b2, 1.f, act, sbh);
    // G4: h = sbh @ w1^T + b1 ; hi(relu(h)) -> sah
    gemm_mma<0,0,1><<<grid, 256, SMEM_TOTAL>>>(sbh, wt + 1*WSZ, b1, 1.f, act, sah);
    // G5: act += sah @ w2^T + b2
    gemm_mma<1,1,0><<<grid, 256, SMEM_TOTAL>>>(sah, wt + 2*WSZ, b2, 1.f, act, sbh);

    ang_kernel<<<NROWS / 8, 256>>>(act, w_ang, b_ang, angb);

    float* out = (float*)d_out;
    float* out_angles = out;
    float* out_pred   = out + (size_t)NROWS * 14;
    float* out_frames = out + (size_t)NROWS * 56;
    epilogue_kernel<<<(NROWS + 127) / 128, 128>>>(
        angb, rigids, def_frames, lit_pos, atom_mask, aatype, gidx,
        out_angles, out_pred, out_frames);
}

// round 12
// speedup vs baseline: 6.1680x; 1.0669x over previous
#include <cuda_runtime.h>
#include <cuda_fp16.h>
#include <math.h>
#include <stdint.h>

#define NROWS 32768
#define DIM 1024
#define NRES 21

// ---------------- scratch (no cudaMalloc allowed) ----------------
__device__ float g_act[(size_t)NROWS * DIM];
__device__ float g_ang[(size_t)NROWS * 14];
__device__ float g_wangT[14 * DIM];                 // transposed w_ang [14][1024]
__device__ __half g_wt[3][(size_t)DIM * DIM];       // transposed fp16 weights [n][k]
__device__ __half g_sa_hi[(size_t)NROWS * DIM];     // activation hi ping
__device__ __half g_sb_hi[(size_t)NROWS * DIM];     // activation hi pong

// ---------------- PTX helpers (baseline compute_103 safe) ----------------
__device__ __forceinline__ uint32_t smem_to_u32(const void* p) {
    uint32_t a;
    asm("{ .reg .u64 t; cvta.to.shared.u64 t, %1; cvt.u32.u64 %0, t; }" : "=r"(a) : "l"(p));
    return a;
}
__device__ __forceinline__ void ldsm4(uint32_t (&r)[4], uint32_t addr) {
    asm volatile("ldmatrix.sync.aligned.m8n8.x4.shared.b16 {%0,%1,%2,%3}, [%4];"
                 : "=r"(r[0]), "=r"(r[1]), "=r"(r[2]), "=r"(r[3]) : "r"(addr));
}
__device__ __forceinline__ void mma_f16(float* d, const uint32_t* a, const uint32_t* b) {
    asm("mma.sync.aligned.m16n8k16.row.col.f32.f16.f16.f32 "
        "{%0,%1,%2,%3}, {%4,%5,%6,%7}, {%8,%9}, {%0,%1,%2,%3};"
        : "+f"(d[0]), "+f"(d[1]), "+f"(d[2]), "+f"(d[3])
        : "r"(a[0]), "r"(a[1]), "r"(a[2]), "r"(a[3]), "r"(b[0]), "r"(b[1]));
}
__device__ __forceinline__ void cp16(uint32_t dst, const void* src) {
    asm volatile("cp.async.cg.shared.global [%0], [%1], 16;" :: "r"(dst), "l"(src));
}
__device__ __forceinline__ void cp_commit() {
    asm volatile("cp.async.commit_group;" ::: "memory");
}
template<int N>
__device__ __forceinline__ void cp_wait() {
    asm volatile("cp.async.wait_group %0;" :: "n"(N) : "memory");
}
__device__ __forceinline__ uint32_t pack_h2(__half x, __half y) {
    __half2 t; t.x = x; t.y = y;
    return *(uint32_t*)&t;
}

// ---------------- GEMM (all single-plane fp16) ----------------
#define KCHUNK 32
#define NITERS (DIM / KCHUNK)
#define TILE_S 16384
#define STAGE_S (2 * TILE_S)
#define NSTAGE 3
#define SMEM_TOTAL (NSTAGE * STAGE_S)   // 98304

// RESID: C += prev C ; WC: write fp32 C ; WSPLIT: write fp16 hi of relu(C)
template<int RESID, int WC, int WSPLIT>
__global__ __launch_bounds__(256, 2) void gemm_mma(
    const __half* __restrict__ Ah, const __half* __restrict__ Bh,
    const float* __restrict__ bias, float bias_scale,
    float* __restrict__ C, __half* __restrict__ Shi)
{
    extern __shared__ char smem[];
    const uint32_t sb = smem_to_u32(smem);
    const int tid = threadIdx.x;
    const int wid = tid >> 5;
    const int lane = tid & 31;
    const int bx = blockIdx.x, by = blockIdx.y;
    const int wm = wid & 3;
    const int wn = wid >> 2;

    float d[2][8][4];
    #pragma unroll
    for (int i = 0; i < 2; i++)
        #pragma unroll
        for (int j = 0; j < 8; j++)
            #pragma unroll
            for (int q = 0; q < 4; q++) d[i][j][q] = 0.f;

    auto issue = [&](int kc) {
        const int s = kc % NSTAGE;
        const uint32_t stage = sb + s * STAGE_S;
        #pragma unroll
        for (int t = 0; t < 4; t++) {
            const int i = tid + t * 256;
            const char* src;
            uint32_t dst;
            if (i < 512) {
                const int row = i >> 2;
                const int unit = i & 3;
                src = (const char*)Ah + (size_t)(by * 128 + row) * (DIM * 2)
                      + kc * 64 + unit * 16;
                dst = stage + row * 128 + ((unit ^ (row & 7)) << 4);
            } else {
                const int j = i - 512;
                const int row = j >> 2;
                const int unit = j & 3;
                src = (const char*)Bh + (size_t)(bx * 128 + row) * (DIM * 2)
                      + kc * 64 + unit * 16;
                dst = stage + TILE_S + row * 128 + ((unit ^ (row & 7)) << 4);
            }
            cp16(dst, src);
        }
        cp_commit();
    };

    issue(0);
    issue(1);

    for (int kc = 0; kc < NITERS; kc++) {
        cp_wait<1>();
        __syncthreads();
        if (kc + 2 < NITERS) issue(kc + 2);

        const uint32_t stage = sb + (kc % NSTAGE) * STAGE_S;
        #pragma unroll
        for (int kh = 0; kh < 2; kh++) {
            uint32_t ah[2][4];
            const int aunit = kh * 2 + (lane >> 4);
            #pragma unroll
            for (int mt = 0; mt < 2; mt++) {
                const int arow = wm * 32 + mt * 16 + (lane & 15);
                ldsm4(ah[mt], stage + arow * 128 + ((aunit ^ (arow & 7)) << 4));
            }
            const int bunit = kh * 2 + ((lane >> 3) & 1);
            #pragma unroll
            for (int ntp = 0; ntp < 4; ntp++) {
                const int brow = wn * 64 + ntp * 16 + (lane & 7) + (((lane >> 4) & 1) << 3);
                uint32_t bh[4];
                ldsm4(bh, stage + TILE_S + brow * 128 + ((bunit ^ (brow & 7)) << 4));
                #pragma unroll
                for (int mt = 0; mt < 2; mt++) {
                    #pragma unroll
                    for (int c = 0; c < 2; c++)
                        mma_f16(d[mt][ntp * 2 + c], ah[mt], &bh[2 * c]);
                }
            }
        }
    }

    // ---- epilogue ----
    const int rq = lane >> 2;
    const int cq = (lane & 3) * 2;
    #pragma unroll
    for (int mt = 0; mt < 2; mt++) {
        #pragma unroll
        for (int nt = 0; nt < 8; nt++) {
            const int col = bx * 128 + wn * 64 + nt * 8 + cq;
            const float b0 = bias_scale * bias[col];
            const float b1 = bias_scale * bias[col + 1];
            #pragma unroll
            for (int hrow = 0; hrow < 2; hrow++) {
                const int row = by * 128 + wm * 32 + mt * 16 + rq + hrow * 8;
                float vx = d[mt][nt][hrow * 2 + 0] + b0;
                float vy = d[mt][nt][hrow * 2 + 1] + b1;
                float* cp = C + (size_t)row * DIM + col;
                if (RESID) {
                    float2 old = *(const float2*)cp;
                    vx += old.x; vy += old.y;
                }
                if (WC) *(float2*)cp = make_float2(vx, vy);
                if (WSPLIT) {
                    const size_t o = (size_t)row * DIM + col;
                    *(uint32_t*)(Shi + o) = pack_h2(__float2half(fmaxf(vx, 0.f)),
                                                    __float2half(fmaxf(vy, 0.f)));
                }
            }
        }
    }
}

// ---------------- fuse0: fp16(relu(rep0)+relu(rep1)) ----------------
__global__ __launch_bounds__(256) void fuse0(
    const float* __restrict__ rep0, const float* __restrict__ rep1,
    __half* __restrict__ Shi)
{
    const size_t i = ((size_t)blockIdx.x * blockDim.x + threadIdx.x) * 4;
    float4 a = *(const float4*)(rep0 + i);
    float4 b = *(const float4*)(rep1 + i);
    float v0 = fmaxf(a.x, 0.f) + fmaxf(b.x, 0.f);
    float v1 = fmaxf(a.y, 0.f) + fmaxf(b.y, 0.f);
    float v2 = fmaxf(a.z, 0.f) + fmaxf(b.z, 0.f);
    float v3 = fmaxf(a.w, 0.f) + fmaxf(b.w, 0.f);
    uint2 o;
    o.x = pack_h2(__float2half(v0), __float2half(v1));
    o.y = pack_h2(__float2half(v2), __float2half(v3));
    *(uint2*)(Shi + i) = o;
}

// ---------------- weight transpose to fp16 ----------------
__global__ __launch_bounds__(256) void prep_w(const float* __restrict__ W,
                                              __half* __restrict__ Wt)
{
    __shared__ float t[32][33];
    const int n0 = blockIdx.x * 32, k0 = blockIdx.y * 32;
    const int tx = threadIdx.x, ty = threadIdx.y;  // (32, 8)
    #pragma unroll
    for (int i = 0; i < 4; i++)
        t[ty + i * 8][tx] = W[(size_t)(k0 + ty + i * 8) * DIM + n0 + tx];
    __syncthreads();
    #pragma unroll
    for (int i = 0; i < 4; i++)
        Wt[(size_t)(n0 + ty + i * 8) * DIM + k0 + tx] = __float2half(t[tx][ty + i * 8]);
}

// ---------------- w_ang transpose (exact fp32 copy): wT[j][i] = w[i][j] ----------------
__global__ __launch_bounds__(256) void prep_wang(const float* __restrict__ W,
                                                 float* __restrict__ WT)
{
    const int idx = blockIdx.x * 256 + threadIdx.x;   // 14*1024 total
    if (idx >= 14 * DIM) return;
    const int j = idx / DIM;
    const int i = idx % DIM;
    WT[j * DIM + i] = W[i * 14 + j];
}

// ---------------- torsion head: coalesced via transposed w_ang ----------------
// Bitwise-identical to the previous version: same multiplicands, same FMA order,
// same shuffle reduction — only the w-load addressing is coalesced now.
__global__ __launch_bounds__(256) void ang_kernel(
    const float* __restrict__ act, const float* __restrict__ wT,
    const float* __restrict__ b_ang, float* __restrict__ angbuf)
{
    const int gw = (int)((blockIdx.x * blockDim.x + threadIdx.x) >> 5);
    const int lane = threadIdx.x & 31;
    if (gw >= NROWS) return;
    const float* row = act + (size_t)gw * DIM;
    float acc[14] = {};
    for (int i = lane; i < DIM; i += 32) {
        float a = fmaxf(row[i], 0.f);
        #pragma unroll
        for (int j = 0; j < 14; j++) acc[j] = fmaf(a, wT[j * DIM + i], acc[j]);
    }
    #pragma unroll
    for (int j = 0; j < 14; j++) {
        #pragma unroll
        for (int off = 16; off; off >>= 1)
            acc[j] += __shfl_down_sync(0xffffffffu, acc[j], off);
    }
    if (lane == 0) {
        float* o = angbuf + (size_t)gw * 14;
        #pragma unroll
        for (int j = 0; j < 14; j++) o[j] = acc[j] + b_ang[j];
    }
}

// ---------------- per-residue geometry ----------------
__global__ __launch_bounds__(128) void epilogue_kernel(
    const float* __restrict__ angbuf,
    const float* __restrict__ rigids, const float* __restrict__ def_frames,
    const float* __restrict__ lit_pos, const float* __restrict__ atom_mask,
    const int* __restrict__ aatype, const int* __restrict__ gidx,
    float* __restrict__ out_angles, float* __restrict__ out_pred,
    float* __restrict__ out_frames)
{
    const int n = blockIdx.x * blockDim.x + threadIdx.x;
    if (n >= NROWS) return;
    const int aa = aatype[n];

    float s[8], c[8];
    s[0] = 0.f; c[0] = 1.f;
    #pragma unroll
    for (int i = 0; i < 7; i++) {
        float ss = angbuf[(size_t)n * 14 + 2 * i];
        float cc = angbuf[(size_t)n * 14 + 2 * i + 1];
        float inv = rsqrtf(fmaxf(ss * ss + cc * cc, 1e-12f));
        ss *= inv; cc *= inv;
        s[i + 1] = ss; c[i + 1] = cc;
        out_angles[(size_t)n * 14 + 2 * i] = ss;
        out_angles[(size_t)n * 14 + 2 * i + 1] = cc;
    }

    float FR[8][9], FT[8][3];
    #pragma unroll
    for (int k = 0; k < 8; k++) {
        const float* D = def_frames + ((size_t)aa * 8 + k) * 16;
        #pragma unroll
        for (int r = 0; r < 3; r++) {
            float d1 = D[r * 4 + 1], d2 = D[r * 4 + 2];
            FR[k][r * 3 + 0] = D[r * 4 + 0];
            FR[k][r * 3 + 1] = c[k] * d1 + s[k] * d2;
            FR[k][r * 3 + 2] = -s[k] * d1 + c[k] * d2;
            FT[k][r] = D[r * 4 + 3];
        }
    }

    #pragma unroll
    for (int k = 5; k <= 7; k++) {
        float R[9], T[3];
        #pragma unroll
        for (int r = 0; r < 3; r++) {
            #pragma unroll
            for (int cc2 = 0; cc2 < 3; cc2++)
                R[r * 3 + cc2] = FR[k - 1][r * 3 + 0] * FR[k][0 + cc2]
                               + FR[k - 1][r * 3 + 1] * FR[k][3 + cc2]
                               + FR[k - 1][r * 3 + 2] * FR[k][6 + cc2];
            T[r] = FR[k - 1][r * 3 + 0] * FT[k][0]
                 + FR[k - 1][r * 3 + 1] * FT[k][1]
                 + FR[k - 1][r * 3 + 2] * FT[k][2] + FT[k - 1][r];
        }
        #pragma unroll
        for (int q = 0; q < 9; q++) FR[k][q] = R[q];
        FT[k][0] = T[0]; FT[k][1] = T[1]; FT[k][2] = T[2];
    }

    const float* rg = rigids + (size_t)n * 16;
    float R0[9] = {rg[0], rg[1], rg[2], rg[4], rg[5], rg[6], rg[8], rg[9], rg[10]};
    float t0[3] = {rg[3], rg[7], rg[11]};

    #pragma unroll
    for (int k = 0; k < 8; k++) {
        float R[9], T[3];
        #pragma unroll
        for (int r = 0; r < 3; r++) {
            #pragma unroll
            for (int cc2 = 0; cc2 < 3; cc2++)
                R[r * 3 + cc2] = R0[r * 3 + 0] * FR[k][0 + cc2]
                               + R0[r * 3 + 1] * FR[k][3 + cc2]
                               + R0[r * 3 + 2] * FR[k][6 + cc2];
            T[r] = R0[r * 3 + 0] * FT[k][0] + R0[r * 3 + 1] * FT[k][1]
                 + R0[r * 3 + 2] * FT[k][2] + t0[r];
        }
        #pragma unroll
        for (int q = 0; q < 9; q++) FR[k][q] = R[q];
        FT[k][0] = T[0]; FT[k][1] = T[1]; FT[k][2] = T[2];

        float* of = out_frames + ((size_t)n * 8 + k) * 16;
        of[0]  = R[0]; of[1]  = R[1]; of[2]  = R[2]; of[3]  = T[0];
        of[4]  = R[3]; of[5]  = R[4]; of[6]  = R[5]; of[7]  = T[1];
        of[8]  = R[6]; of[9]  = R[7]; of[10] = R[8]; of[11] = T[2];
        of[12] = 0.f;  of[13] = 0.f;  of[14] = 0.f;  of[15] = 1.f;
    }

    #pragma unroll
    for (int a = 0; a < 14; a++) {
        int g = gidx[aa * 14 + a];
        const float* p = lit_pos + ((size_t)aa * 14 + a) * 3;
        float m = atom_mask[aa * 14 + a];
        float px = p[0], py = p[1], pz = p[2];
        float* op = out_pred + ((size_t)n * 14 + a) * 3;
        op[0] = (FR[g][0] * px + FR[g][1] * py + FR[g][2] * pz + FT[g][0]) * m;
        op[1] = (FR[g][3] * px + FR[g][4] * py + FR[g][5] * pz + FT[g][1]) * m;
        op[2] = (FR[g][6] * px + FR[g][7] * py + FR[g][8] * pz + FT[g][2]) * m;
    }
}

// ---------------- launch ----------------
extern "C" void kernel_launch(void* const* d_in, const int* in_sizes, int n_in,
                              void* d_out, int out_size)
{
    const float* rep0       = (const float*)d_in[0];
    const float* rep1       = (const float*)d_in[1];
    const float* w_in       = (const float*)d_in[2];
    const float* b_in       = (const float*)d_in[3];
    const float* w1         = (const float*)d_in[4];
    const float* b1         = (const float*)d_in[5];
    const float* w2         = (const float*)d_in[6];
    const float* b2         = (const float*)d_in[7];
    const float* w_ang      = (const float*)d_in[8];
    const float* b_ang      = (const float*)d_in[9];
    const float* rigids     = (const float*)d_in[10];
    const float* def_frames = (const float*)d_in[11];
    const float* lit_pos    = (const float*)d_in[12];
    const float* atom_mask  = (const float*)d_in[13];
    const int*   aatype     = (const int*)d_in[14];
    const int*   gidx       = (const int*)d_in[15];

    float *act, *angb, *wangT;
    __half *wt, *sah, *sbh;
    cudaGetSymbolAddress((void**)&act, g_act);
    cudaGetSymbolAddress((void**)&angb, g_ang);
    cudaGetSymbolAddress((void**)&wangT, g_wangT);
    cudaGetSymbolAddress((void**)&wt, g_wt);
    cudaGetSymbolAddress((void**)&sah, g_sa_hi);
    cudaGetSymbolAddress((void**)&sbh, g_sb_hi);
    const size_t WSZ = (size_t)DIM * DIM;

    cudaFuncSetAttribute(gemm_mma<0,1,1>, cudaFuncAttributeMaxDynamicSharedMemorySize, SMEM_TOTAL);
    cudaFuncSetAttribute(gemm_mma<0,0,1>, cudaFuncAttributeMaxDynamicSharedMemorySize, SMEM_TOTAL);
    cudaFuncSetAttribute(gemm_mma<1,1,1>, cudaFuncAttributeMaxDynamicSharedMemorySize, SMEM_TOTAL);
    cudaFuncSetAttribute(gemm_mma<1,1,0>, cudaFuncAttributeMaxDynamicSharedMemorySize, SMEM_TOTAL);

    dim3 pg(DIM / 32, DIM / 32), pb(32, 8);
    prep_w<<<pg, pb>>>(w_in, wt + 0 * WSZ);
    prep_w<<<pg, pb>>>(w1,   wt + 1 * WSZ);
    prep_w<<<pg, pb>>>(w2,   wt + 2 * WSZ);
    prep_wang<<<(14 * DIM + 255) / 256, 256>>>(w_ang, wangT);

    fuse0<<<(NROWS * DIM) / (256 * 4), 256>>>(rep0, rep1, sah);

    dim3 grid(DIM / 128, NROWS / 128);  // (8, 256)

    // G1: act = sah @ w_in^T + 2*b_in ; hi(relu(act)) -> sbh
    gemm_mma<0,1,1><<<grid, 256, SMEM_TOTAL>>>(sah, wt + 0*WSZ, b_in, 2.f, act, sbh);
    // G2: h = sbh @ w1^T + b1 ; hi(relu(h)) -> sah
    gemm_mma<0,0,1><<<grid, 256, SMEM_TOTAL>>>(sbh, wt + 1*WSZ, b1, 1.f, act, sah);
    // G3: act += sah @ w2^T + b2 ; hi(relu(act)) -> sbh
    gemm_mma<1,1,1><<<grid, 256, SMEM_TOTAL>>>(sah, wt + 2*WSZ, b2, 1.f, act, sbh);
    // G4: h = sbh @ w1^T + b1 ; hi(relu(h)) -> sah
    gemm_mma<0,0,1><<<grid, 256, SMEM_TOTAL>>>(sbh, wt + 1*WSZ, b1, 1.f, act, sah);
    // G5: act += sah @ w2^T + b2
    gemm_mma<1,1,0><<<grid, 256, SMEM_TOTAL>>>(sah, wt + 2*WSZ, b2, 1.f, act, sbh);

    ang_kernel<<<NROWS / 8, 256>>>(act, wangT, b_ang, angb);

    float* out = (float*)d_out;
    float* out_angles = out;
    float* out_pred   = out + (size_t)NROWS * 14;
    float* out_frames = out + (size_t)NROWS * 56;
    epilogue_kernel<<<(NROWS + 127) / 128, 128>>>(
        angb, rigids, def_frames, lit_pos, atom_mask, aatype, gidx,
        out_angles, out_pred, out_frames);
}

// round 13
// speedup vs baseline: 6.9028x; 1.1191x over previous
#include <cuda_runtime.h>
#include <cuda_fp16.h>
#include <math.h>
#include <stdint.h>

#define NROWS 32768
#define DIM 1024
#define NRES 21

// ---------------- scratch (no cudaMalloc allowed) ----------------
__device__ float g_act[(size_t)NROWS * DIM];
__device__ float g_ang[(size_t)NROWS * 14];
__device__ float g_wangT[14 * DIM];                 // transposed w_ang [14][1024]
__device__ __half g_wt[3][(size_t)DIM * DIM];       // transposed fp16 weights [n][k]
__device__ __half g_sa_hi[(size_t)NROWS * DIM];     // activation hi ping
__device__ __half g_sb_hi[(size_t)NROWS * DIM];     // activation hi pong

// ---------------- PTX helpers (baseline compute_103 safe) ----------------
__device__ __forceinline__ uint32_t smem_to_u32(const void* p) {
    uint32_t a;
    asm("{ .reg .u64 t; cvta.to.shared.u64 t, %1; cvt.u32.u64 %0, t; }" : "=r"(a) : "l"(p));
    return a;
}
__device__ __forceinline__ void ldsm4(uint32_t (&r)[4], uint32_t addr) {
    asm volatile("ldmatrix.sync.aligned.m8n8.x4.shared.b16 {%0,%1,%2,%3}, [%4];"
                 : "=r"(r[0]), "=r"(r[1]), "=r"(r[2]), "=r"(r[3]) : "r"(addr));
}
__device__ __forceinline__ void mma_f16(float* d, const uint32_t* a, const uint32_t* b) {
    asm("mma.sync.aligned.m16n8k16.row.col.f32.f16.f16.f32 "
        "{%0,%1,%2,%3}, {%4,%5,%6,%7}, {%8,%9}, {%0,%1,%2,%3};"
        : "+f"(d[0]), "+f"(d[1]), "+f"(d[2]), "+f"(d[3])
        : "r"(a[0]), "r"(a[1]), "r"(a[2]), "r"(a[3]), "r"(b[0]), "r"(b[1]));
}
__device__ __forceinline__ void cp16(uint32_t dst, const void* src) {
    asm volatile("cp.async.cg.shared.global [%0], [%1], 16;" :: "r"(dst), "l"(src));
}
__device__ __forceinline__ void cp_commit() {
    asm volatile("cp.async.commit_group;" ::: "memory");
}
template<int N>
__device__ __forceinline__ void cp_wait() {
    asm volatile("cp.async.wait_group %0;" :: "n"(N) : "memory");
}
__device__ __forceinline__ uint32_t pack_h2(__half x, __half y) {
    __half2 t; t.x = x; t.y = y;
    return *(uint32_t*)&t;
}

// ---------------- GEMM (single-plane fp16, full 128B rows, K-chunk 64) ----------------
// A/B smem tiles: 128 rows x 128B (64 fp16), units 0-7 all data.
// swizzle: unit' = unit ^ (row & 7)
#define KCHUNK 64
#define NITERS (DIM / KCHUNK)     // 16
#define TILE_S 16384
#define STAGE_S (2 * TILE_S)      // 32768
#define NSTAGE 3
#define SMEM_TOTAL (NSTAGE * STAGE_S)   // 98304

// RESID: C += prev C ; WC: write fp32 C ; WSPLIT: write fp16 hi of relu(C)
template<int RESID, int WC, int WSPLIT>
__global__ __launch_bounds__(256, 2) void gemm_mma(
    const __half* __restrict__ Ah, const __half* __restrict__ Bh,
    const float* __restrict__ bias, float bias_scale,
    float* __restrict__ C, __half* __restrict__ Shi)
{
    extern __shared__ char smem[];
    const uint32_t sb = smem_to_u32(smem);
    const int tid = threadIdx.x;
    const int wid = tid >> 5;
    const int lane = tid & 31;
    const int bx = blockIdx.x, by = blockIdx.y;
    const int wm = wid & 3;
    const int wn = wid >> 2;

    float d[2][8][4];
    #pragma unroll
    for (int i = 0; i < 2; i++)
        #pragma unroll
        for (int j = 0; j < 8; j++)
            #pragma unroll
            for (int q = 0; q < 4; q++) d[i][j][q] = 0.f;

    // producer: A 1024 + B 1024 cp16 units per stage, 8 per thread
    auto issue = [&](int kc) {
        const int s = kc % NSTAGE;
        const uint32_t stage = sb + s * STAGE_S;
        #pragma unroll
        for (int t = 0; t < 8; t++) {
            const int i = tid + t * 256;
            const int tile = i >> 10;          // 0 = A, 1 = B
            const int idx = i & 1023;
            const int row = idx >> 3;
            const int unit = idx & 7;
            const __half* plane = tile ? Bh : Ah;
            const int grow = (tile ? bx : by) * 128 + row;
            const char* src = (const char*)plane + (size_t)grow * (DIM * 2)
                              + kc * 128 + unit * 16;
            const uint32_t dst = stage + tile * TILE_S + row * 128
                                 + ((unit ^ (row & 7)) << 4);
            cp16(dst, src);
        }
        cp_commit();
    };

    issue(0);
    issue(1);

    for (int kc = 0; kc < NITERS; kc++) {
        cp_wait<1>();
        __syncthreads();
        if (kc + 2 < NITERS) issue(kc + 2);

        const uint32_t stage = sb + (kc % NSTAGE) * STAGE_S;
        #pragma unroll
        for (int kh = 0; kh < 4; kh++) {      // four k16 sub-steps (ascending k)
            uint32_t ah[2][4];
            const int aunit = kh * 2 + (lane >> 4);
            #pragma unroll
            for (int mt = 0; mt < 2; mt++) {
                const int arow = wm * 32 + mt * 16 + (lane & 15);
                ldsm4(ah[mt], stage + arow * 128 + ((aunit ^ (arow & 7)) << 4));
            }
            const int bunit = kh * 2 + ((lane >> 3) & 1);
            #pragma unroll
            for (int ntp = 0; ntp < 4; ntp++) {
                const int brow = wn * 64 + ntp * 16 + (lane & 7) + (((lane >> 4) & 1) << 3);
                uint32_t bh[4];
                ldsm4(bh, stage + TILE_S + brow * 128 + ((bunit ^ (brow & 7)) << 4));
                #pragma unroll
                for (int mt = 0; mt < 2; mt++) {
                    #pragma unroll
                    for (int c = 0; c < 2; c++)
                        mma_f16(d[mt][ntp * 2 + c], ah[mt], &bh[2 * c]);
                }
            }
        }
    }

    // ---- epilogue ----
    const int rq = lane >> 2;
    const int cq = (lane & 3) * 2;
    #pragma unroll
    for (int mt = 0; mt < 2; mt++) {
        #pragma unroll
        for (int nt = 0; nt < 8; nt++) {
            const int col = bx * 128 + wn * 64 + nt * 8 + cq;
            const float b0 = bias_scale * bias[col];
            const float b1 = bias_scale * bias[col + 1];
            #pragma unroll
            for (int hrow = 0; hrow < 2; hrow++) {
                const int row = by * 128 + wm * 32 + mt * 16 + rq + hrow * 8;
                float vx = d[mt][nt][hrow * 2 + 0] + b0;
                float vy = d[mt][nt][hrow * 2 + 1] + b1;
                float* cp = C + (size_t)row * DIM + col;
                if (RESID) {
                    float2 old = *(const float2*)cp;
                    vx += old.x; vy += old.y;
                }
                if (WC) *(float2*)cp = make_float2(vx, vy);
                if (WSPLIT) {
                    const size_t o = (size_t)row * DIM + col;
                    *(uint32_t*)(Shi + o) = pack_h2(__float2half(fmaxf(vx, 0.f)),
                                                    __float2half(fmaxf(vy, 0.f)));
                }
            }
        }
    }
}

// ---------------- fuse0: fp16(relu(rep0)+relu(rep1)) ----------------
__global__ __launch_bounds__(256) void fuse0(
    const float* __restrict__ rep0, const float* __restrict__ rep1,
    __half* __restrict__ Shi)
{
    const size_t i = ((size_t)blockIdx.x * blockDim.x + threadIdx.x) * 4;
    float4 a = *(const float4*)(rep0 + i);
    float4 b = *(const float4*)(rep1 + i);
    float v0 = fmaxf(a.x, 0.f) + fmaxf(b.x, 0.f);
    float v1 = fmaxf(a.y, 0.f) + fmaxf(b.y, 0.f);
    float v2 = fmaxf(a.z, 0.f) + fmaxf(b.z, 0.f);
    float v3 = fmaxf(a.w, 0.f) + fmaxf(b.w, 0.f);
    uint2 o;
    o.x = pack_h2(__float2half(v0), __float2half(v1));
    o.y = pack_h2(__float2half(v2), __float2half(v3));
    *(uint2*)(Shi + i) = o;
}

// ---------------- weight transpose to fp16 ----------------
__global__ __launch_bounds__(256) void prep_w(const float* __restrict__ W,
                                              __half* __restrict__ Wt)
{
    __shared__ float t[32][33];
    const int n0 = blockIdx.x * 32, k0 = blockIdx.y * 32;
    const int tx = threadIdx.x, ty = threadIdx.y;  // (32, 8)
    #pragma unroll
    for (int i = 0; i < 4; i++)
        t[ty + i * 8][tx] = W[(size_t)(k0 + ty + i * 8) * DIM + n0 + tx];
    __syncthreads();
    #pragma unroll
    for (int i = 0; i < 4; i++)
        Wt[(size_t)(n0 + ty + i * 8) * DIM + k0 + tx] = __float2half(t[tx][ty + i * 8]);
}

// ---------------- w_ang transpose (exact fp32 copy) ----------------
__global__ __launch_bounds__(256) void prep_wang(const float* __restrict__ W,
                                                 float* __restrict__ WT)
{
    const int idx = blockIdx.x * 256 + threadIdx.x;   // 14*1024 total
    if (idx >= 14 * DIM) return;
    const int j = idx / DIM;
    const int i = idx % DIM;
    WT[j * DIM + i] = W[i * 14 + j];
}

// ---------------- torsion head: coalesced via transposed w_ang ----------------
__global__ __launch_bounds__(256) void ang_kernel(
    const float* __restrict__ act, const float* __restrict__ wT,
    const float* __restrict__ b_ang, float* __restrict__ angbuf)
{
    const int gw = (int)((blockIdx.x * blockDim.x + threadIdx.x) >> 5);
    const int lane = threadIdx.x & 31;
    if (gw >= NROWS) return;
    const float* row = act + (size_t)gw * DIM;
    float acc[14] = {};
    for (int i = lane; i < DIM; i += 32) {
        float a = fmaxf(row[i], 0.f);
        #pragma unroll
        for (int j = 0; j < 14; j++) acc[j] = fmaf(a, wT[j * DIM + i], acc[j]);
    }
    #pragma unroll
    for (int j = 0; j < 14; j++) {
        #pragma unroll
        for (int off = 16; off; off >>= 1)
            acc[j] += __shfl_down_sync(0xffffffffu, acc[j], off);
    }
    if (lane == 0) {
        float* o = angbuf + (size_t)gw * 14;
        #pragma unroll
        for (int j = 0; j < 14; j++) o[j] = acc[j] + b_ang[j];
    }
}

// ---------------- per-residue geometry ----------------
__global__ __launch_bounds__(128) void epilogue_kernel(
    const float* __restrict__ angbuf,
    const float* __restrict__ rigids, const float* __restrict__ def_frames,
    const float* __restrict__ lit_pos, const float* __restrict__ atom_mask,
    const int* __restrict__ aatype, const int* __restrict__ gidx,
    float* __restrict__ out_angles, float* __restrict__ out_pred,
    float* __restrict__ out_frames)
{
    const int n = blockIdx.x * blockDim.x + threadIdx.x;
    if (n >= NROWS) return;
    const int aa = aatype[n];

    float s[8], c[8];
    s[0] = 0.f; c[0] = 1.f;
    #pragma unroll
    for (int i = 0; i < 7; i++) {
        float ss = angbuf[(size_t)n * 14 + 2 * i];
        float cc = angbuf[(size_t)n * 14 + 2 * i + 1];
        float inv = rsqrtf(fmaxf(ss * ss + cc * cc, 1e-12f));
        ss *= inv; cc *= inv;
        s[i + 1] = ss; c[i + 1] = cc;
        out_angles[(size_t)n * 14 + 2 * i] = ss;
        out_angles[(size_t)n * 14 + 2 * i + 1] = cc;
    }

    float FR[8][9], FT[8][3];
    #pragma unroll
    for (int k = 0; k < 8; k++) {
        const float* D = def_frames + ((size_t)aa * 8 + k) * 16;
        #pragma unroll
        for (int r = 0; r < 3; r++) {
            float d1 = D[r * 4 + 1], d2 = D[r * 4 + 2];
            FR[k][r * 3 + 0] = D[r * 4 + 0];
            FR[k][r * 3 + 1] = c[k] * d1 + s[k] * d2;
            FR[k][r * 3 + 2] = -s[k] * d1 + c[k] * d2;
            FT[k][r] = D[r * 4 + 3];
        }
    }

    #pragma unroll
    for (int k = 5; k <= 7; k++) {
        float R[9], T[3];
        #pragma unroll
        for (int r = 0; r < 3; r++) {
            #pragma unroll
            for (int cc2 = 0; cc2 < 3; cc2++)
                R[r * 3 + cc2] = FR[k - 1][r * 3 + 0] * FR[k][0 + cc2]
                               + FR[k - 1][r * 3 + 1] * FR[k][3 + cc2]
                               + FR[k - 1][r * 3 + 2] * FR[k][6 + cc2];
            T[r] = FR[k - 1][r * 3 + 0] * FT[k][0]
                 + FR[k - 1][r * 3 + 1] * FT[k][1]
                 + FR[k - 1][r * 3 + 2] * FT[k][2] + FT[k - 1][r];
        }
        #pragma unroll
        for (int q = 0; q < 9; q++) FR[k][q] = R[q];
        FT[k][0] = T[0]; FT[k][1] = T[1]; FT[k][2] = T[2];
    }

    const float* rg = rigids + (size_t)n * 16;
    float R0[9] = {rg[0], rg[1], rg[2], rg[4], rg[5], rg[6], rg[8], rg[9], rg[10]};
    float t0[3] = {rg[3], rg[7], rg[11]};

    #pragma unroll
    for (int k = 0; k < 8; k++) {
        float R[9], T[3];
        #pragma unroll
        for (int r = 0; r < 3; r++) {
            #pragma unroll
            for (int cc2 = 0; cc2 < 3; cc2++)
                R[r * 3 + cc2] = R0[r * 3 + 0] * FR[k][0 + cc2]
                               + R0[r * 3 + 1] * FR[k][3 + cc2]
                               + R0[r * 3 + 2] * FR[k][6 + cc2];
            T[r] = R0[r * 3 + 0] * FT[k][0] + R0[r * 3 + 1] * FT[k][1]
                 + R0[r * 3 + 2] * FT[k][2] + t0[r];
        }
        #pragma unroll
        for (int q = 0; q < 9; q++) FR[k][q] = R[q];
        FT[k][0] = T[0]; FT[k][1] = T[1]; FT[k][2] = T[2];

        float* of = out_frames + ((size_t)n * 8 + k) * 16;
        of[0]  = R[0]; of[1]  = R[1]; of[2]  = R[2]; of[3]  = T[0];
        of[4]  = R[3]; of[5]  = R[4]; of[6]  = R[5]; of[7]  = T[1];
        of[8]  = R[6]; of[9]  = R[7]; of[10] = R[8]; of[11] = T[2];
        of[12] = 0.f;  of[13] = 0.f;  of[14] = 0.f;  of[15] = 1.f;
    }

    #pragma unroll
    for (int a = 0; a < 14; a++) {
        int g = gidx[aa * 14 + a];
        const float* p = lit_pos + ((size_t)aa * 14 + a) * 3;
        float m = atom_mask[aa * 14 + a];
        float px = p[0], py = p[1], pz = p[2];
        float* op = out_pred + ((size_t)n * 14 + a) * 3;
        op[0] = (FR[g][0] * px + FR[g][1] * py + FR[g][2] * pz + FT[g][0]) * m;
        op[1] = (FR[g][3] * px + FR[g][4] * py + FR[g][5] * pz + FT[g][1]) * m;
        op[2] = (FR[g][6] * px + FR[g][7] * py + FR[g][8] * pz + FT[g][2]) * m;
    }
}

// ---------------- launch ----------------
extern "C" void kernel_launch(void* const* d_in, const int* in_sizes, int n_in,
                              void* d_out, int out_size)
{
    const float* rep0       = (const float*)d_in[0];
    const float* rep1       = (const float*)d_in[1];
    const float* w_in       = (const float*)d_in[2];
    const float* b_in       = (const float*)d_in[3];
    const float* w1         = (const float*)d_in[4];
    const float* b1         = (const float*)d_in[5];
    const float* w2         = (const float*)d_in[6];
    const float* b2         = (const float*)d_in[7];
    const float* w_ang      = (const float*)d_in[8];
    const float* b_ang      = (const float*)d_in[9];
    const float* rigids     = (const float*)d_in[10];
    const float* def_frames = (const float*)d_in[11];
    const float* lit_pos    = (const float*)d_in[12];
    const float* atom_mask  = (const float*)d_in[13];
    const int*   aatype     = (const int*)d_in[14];
    const int*   gidx       = (const int*)d_in[15];

    float *act, *angb, *wangT;
    __half *wt, *sah, *sbh;
    cudaGetSymbolAddress((void**)&act, g_act);
    cudaGetSymbolAddress((void**)&angb, g_ang);
    cudaGetSymbolAddress((void**)&wangT, g_wangT);
    cudaGetSymbolAddress((void**)&wt, g_wt);
    cudaGetSymbolAddress((void**)&sah, g_sa_hi);
    cudaGetSymbolAddress((void**)&sbh, g_sb_hi);
    const size_t WSZ = (size_t)DIM * DIM;

    cudaFuncSetAttribute(gemm_mma<0,1,1>, cudaFuncAttributeMaxDynamicSharedMemorySize, SMEM_TOTAL);
    cudaFuncSetAttribute(gemm_mma<0,0,1>, cudaFuncAttributeMaxDynamicSharedMemorySize, SMEM_TOTAL);
    cudaFuncSetAttribute(gemm_mma<1,1,1>, cudaFuncAttributeMaxDynamicSharedMemorySize, SMEM_TOTAL);
    cudaFuncSetAttribute(gemm_mma<1,1,0>, cudaFuncAttributeMaxDynamicSharedMemorySize, SMEM_TOTAL);

    dim3 pg(DIM / 32, DIM / 32), pb(32, 8);
    prep_w<<<pg, pb>>>(w_in, wt + 0 * WSZ);
    prep_w<<<pg, pb>>>(w1,   wt + 1 * WSZ);
    prep_w<<<pg, pb>>>(w2,   wt + 2 * WSZ);
    prep_wang<<<(14 * DIM + 255) / 256, 256>>>(w_ang, wangT);

    fuse0<<<(NROWS * DIM) / (256 * 4), 256>>>(rep0, rep1, sah);

    dim3 grid(DIM / 128, NROWS / 128);  // (8, 256)

    // G1: act = sah @ w_in^T + 2*b_in ; hi(relu(act)) -> sbh
    gemm_mma<0,1,1><<<grid, 256, SMEM_TOTAL>>>(sah, wt + 0*WSZ, b_in, 2.f, act, sbh);
    // G2: h = sbh @ w1^T + b1 ; hi(relu(h)) -> sah
    gemm_mma<0,0,1><<<grid, 256, SMEM_TOTAL>>>(sbh, wt + 1*WSZ, b1, 1.f, act, sah);
    // G3: act += sah @ w2^T + b2 ; hi(relu(act)) -> sbh
    gemm_mma<1,1,1><<<grid, 256, SMEM_TOTAL>>>(sah, wt + 2*WSZ, b2, 1.f, act, sbh);
    // G4: h = sbh @ w1^T + b1 ; hi(relu(h)) -> sah
    gemm_mma<0,0,1><<<grid, 256, SMEM_TOTAL>>>(sbh, wt + 1*WSZ, b1, 1.f, act, sah);
    // G5: act += sah @ w2^T + b2
    gemm_mma<1,1,0><<<grid, 256, SMEM_TOTAL>>>(sah, wt + 2*WSZ, b2, 1.f, act, sbh);

    ang_kernel<<<NROWS / 8, 256>>>(act, wangT, b_ang, angb);

    float* out = (float*)d_out;
    float* out_angles = out;
    float* out_pred   = out + (size_t)NROWS * 14;
    float* out_frames = out + (size_t)NROWS * 56;
    epilogue_kernel<<<(NROWS + 127) / 128, 128>>>(
        angb, rigids, def_frames, lit_pos, atom_mask, aatype, gidx,
        out_angles, out_pred, out_frames);
}

// round 14
// speedup vs baseline: 7.2756x; 1.0540x over previous
#include <cuda_runtime.h>
#include <cuda_fp16.h>
#include <math.h>
#include <stdint.h>

#define NROWS 32768
#define DIM 1024
#define NRES 21

// ---------------- scratch (no cudaMalloc allowed) ----------------
__device__ float g_act[(size_t)NROWS * DIM];
__device__ float g_ang[(size_t)NROWS * 14];
__device__ float g_wangT[14 * DIM];                 // transposed w_ang [14][1024]
__device__ __half g_wt[3][(size_t)DIM * DIM];       // transposed fp16 weights [n][k]
__device__ __half g_sa_hi[(size_t)NROWS * DIM];     // activation hi ping
__device__ __half g_sb_hi[(size_t)NROWS * DIM];     // activation hi pong

// ---------------- PTX helpers (baseline compute_103 safe) ----------------
__device__ __forceinline__ uint32_t smem_to_u32(const void* p) {
    uint32_t a;
    asm("{ .reg .u64 t; cvta.to.shared.u64 t, %1; cvt.u32.u64 %0, t; }" : "=r"(a) : "l"(p));
    return a;
}
__device__ __forceinline__ void ldsm4(uint32_t (&r)[4], uint32_t addr) {
    asm volatile("ldmatrix.sync.aligned.m8n8.x4.shared.b16 {%0,%1,%2,%3}, [%4];"
                 : "=r"(r[0]), "=r"(r[1]), "=r"(r[2]), "=r"(r[3]) : "r"(addr));
}
__device__ __forceinline__ void mma_f16(float* d, const uint32_t* a, const uint32_t* b) {
    asm("mma.sync.aligned.m16n8k16.row.col.f32.f16.f16.f32 "
        "{%0,%1,%2,%3}, {%4,%5,%6,%7}, {%8,%9}, {%0,%1,%2,%3};"
        : "+f"(d[0]), "+f"(d[1]), "+f"(d[2]), "+f"(d[3])
        : "r"(a[0]), "r"(a[1]), "r"(a[2]), "r"(a[3]), "r"(b[0]), "r"(b[1]));
}
__device__ __forceinline__ void cp16(uint32_t dst, const void* src) {
    asm volatile("cp.async.cg.shared.global [%0], [%1], 16;" :: "r"(dst), "l"(src));
}
__device__ __forceinline__ void cp_commit() {
    asm volatile("cp.async.commit_group;" ::: "memory");
}
template<int N>
__device__ __forceinline__ void cp_wait() {
    asm volatile("cp.async.wait_group %0;" :: "n"(N) : "memory");
}
__device__ __forceinline__ uint32_t pack_h2(__half x, __half y) {
    __half2 t; t.x = x; t.y = y;
    return *(uint32_t*)&t;
}

// ---------------- GEMM (single-plane fp16, 128B rows, K-chunk 64, B prefetch) ----------------
#define KCHUNK 64
#define NITERS (DIM / KCHUNK)     // 16
#define TILE_S 16384
#define STAGE_S (2 * TILE_S)      // 32768
#define NSTAGE 3
#define SMEM_TOTAL (NSTAGE * STAGE_S)   // 98304

// RESID: C += prev C ; WC: write fp32 C ; WSPLIT: write fp16 hi of relu(C)
template<int RESID, int WC, int WSPLIT>
__global__ __launch_bounds__(256, 2) void gemm_mma(
    const __half* __restrict__ Ah, const __half* __restrict__ Bh,
    const float* __restrict__ bias, float bias_scale,
    float* __restrict__ C, __half* __restrict__ Shi)
{
    extern __shared__ char smem[];
    const uint32_t sb = smem_to_u32(smem);
    const int tid = threadIdx.x;
    const int wid = tid >> 5;
    const int lane = tid & 31;
    const int bx = blockIdx.x, by = blockIdx.y;
    const int wm = wid & 3;
    const int wn = wid >> 2;

    float d[2][8][4];
    #pragma unroll
    for (int i = 0; i < 2; i++)
        #pragma unroll
        for (int j = 0; j < 8; j++)
            #pragma unroll
            for (int q = 0; q < 4; q++) d[i][j][q] = 0.f;

    auto issue = [&](int kc) {
        const int s = kc % NSTAGE;
        const uint32_t stage = sb + s * STAGE_S;
        #pragma unroll
        for (int t = 0; t < 8; t++) {
            const int i = tid + t * 256;
            const int tile = i >> 10;          // 0 = A, 1 = B
            const int idx = i & 1023;
            const int row = idx >> 3;
            const int unit = idx & 7;
            const __half* plane = tile ? Bh : Ah;
            const int grow = (tile ? bx : by) * 128 + row;
            const char* src = (const char*)plane + (size_t)grow * (DIM * 2)
                              + kc * 128 + unit * 16;
            const uint32_t dst = stage + tile * TILE_S + row * 128
                                 + ((unit ^ (row & 7)) << 4);
            cp16(dst, src);
        }
        cp_commit();
    };

    issue(0);
    issue(1);

    for (int kc = 0; kc < NITERS; kc++) {
        cp_wait<1>();
        __syncthreads();
        if (kc + 2 < NITERS) issue(kc + 2);

        const uint32_t stage = sb + (kc % NSTAGE) * STAGE_S;
        #pragma unroll
        for (int kh = 0; kh < 4; kh++) {
            uint32_t ah[2][4];
            const int aunit = kh * 2 + (lane >> 4);
            #pragma unroll
            for (int mt = 0; mt < 2; mt++) {
                const int arow = wm * 32 + mt * 16 + (lane & 15);
                ldsm4(ah[mt], stage + arow * 128 + ((aunit ^ (arow & 7)) << 4));
            }
            const int bunit = kh * 2 + ((lane >> 3) & 1);
            const int brlane = (lane & 7) + (((lane >> 4) & 1) << 3);
            auto baddr = [&](int ntp) {
                const int brow = wn * 64 + ntp * 16 + brlane;
                return stage + TILE_S + brow * 128 + ((bunit ^ (brow & 7)) << 4);
            };
            uint32_t bh[2][4];
            ldsm4(bh[0], baddr(0));
            #pragma unroll
            for (int ntp = 0; ntp < 4; ntp++) {
                const int cur = ntp & 1;
                if (ntp < 3) ldsm4(bh[cur ^ 1], baddr(ntp + 1));  // prefetch next group
                #pragma unroll
                for (int mt = 0; mt < 2; mt++) {
                    #pragma unroll
                    for (int c = 0; c < 2; c++)
                        mma_f16(d[mt][ntp * 2 + c], ah[mt], &bh[cur][2 * c]);
                }
            }
        }
    }

    // ---- epilogue ----
    const int rq = lane >> 2;
    const int cq = (lane & 3) * 2;
    #pragma unroll
    for (int mt = 0; mt < 2; mt++) {
        #pragma unroll
        for (int nt = 0; nt < 8; nt++) {
            const int col = bx * 128 + wn * 64 + nt * 8 + cq;
            const float b0 = bias_scale * bias[col];
            const float b1 = bias_scale * bias[col + 1];
            #pragma unroll
            for (int hrow = 0; hrow < 2; hrow++) {
                const int row = by * 128 + wm * 32 + mt * 16 + rq + hrow * 8;
                float vx = d[mt][nt][hrow * 2 + 0] + b0;
                float vy = d[mt][nt][hrow * 2 + 1] + b1;
                float* cp = C + (size_t)row * DIM + col;
                if (RESID) {
                    float2 old = *(const float2*)cp;
                    vx += old.x; vy += old.y;
                }
                if (WC) *(float2*)cp = make_float2(vx, vy);
                if (WSPLIT) {
                    const size_t o = (size_t)row * DIM + col;
                    *(uint32_t*)(Shi + o) = pack_h2(__float2half(fmaxf(vx, 0.f)),
                                                    __float2half(fmaxf(vy, 0.f)));
                }
            }
        }
    }
}

// ---------------- fuse0: fp16(relu(rep0)+relu(rep1)) ----------------
__global__ __launch_bounds__(256) void fuse0(
    const float* __restrict__ rep0, const float* __restrict__ rep1,
    __half* __restrict__ Shi)
{
    const size_t i = ((size_t)blockIdx.x * blockDim.x + threadIdx.x) * 4;
    float4 a = *(const float4*)(rep0 + i);
    float4 b = *(const float4*)(rep1 + i);
    float v0 = fmaxf(a.x, 0.f) + fmaxf(b.x, 0.f);
    float v1 = fmaxf(a.y, 0.f) + fmaxf(b.y, 0.f);
    float v2 = fmaxf(a.z, 0.f) + fmaxf(b.z, 0.f);
    float v3 = fmaxf(a.w, 0.f) + fmaxf(b.w, 0.f);
    uint2 o;
    o.x = pack_h2(__float2half(v0), __float2half(v1));
    o.y = pack_h2(__float2half(v2), __float2half(v3));
    *(uint2*)(Shi + i) = o;
}

// ---------------- weight transpose to fp16 ----------------
__global__ __launch_bounds__(256) void prep_w(const float* __restrict__ W,
                                              __half* __restrict__ Wt)
{
    __shared__ float t[32][33];
    const int n0 = blockIdx.x * 32, k0 = blockIdx.y * 32;
    const int tx = threadIdx.x, ty = threadIdx.y;  // (32, 8)
    #pragma unroll
    for (int i = 0; i < 4; i++)
        t[ty + i * 8][tx] = W[(size_t)(k0 + ty + i * 8) * DIM + n0 + tx];
    __syncthreads();
    #pragma unroll
    for (int i = 0; i < 4; i++)
        Wt[(size_t)(n0 + ty + i * 8) * DIM + k0 + tx] = __float2half(t[tx][ty + i * 8]);
}

// ---------------- w_ang transpose (exact fp32 copy) ----------------
__global__ __launch_bounds__(256) void prep_wang(const float* __restrict__ W,
                                                 float* __restrict__ WT)
{
    const int idx = blockIdx.x * 256 + threadIdx.x;   // 14*1024 total
    if (idx >= 14 * DIM) return;
    const int j = idx / DIM;
    const int i = idx % DIM;
    WT[j * DIM + i] = W[i * 14 + j];
}

// ---------------- torsion head: coalesced, float4 loads ----------------
__global__ __launch_bounds__(256) void ang_kernel(
    const float* __restrict__ act, const float* __restrict__ wT,
    const float* __restrict__ b_ang, float* __restrict__ angbuf)
{
    const int gw = (int)((blockIdx.x * blockDim.x + threadIdx.x) >> 5);
    const int lane = threadIdx.x & 31;
    if (gw >= NROWS) return;
    const float4* row = (const float4*)(act + (size_t)gw * DIM);
    float acc[14] = {};
    #pragma unroll
    for (int it = 0; it < 8; it++) {
        const int i4 = lane + it * 32;          // float4 index
        float4 a4 = row[i4];
        float a[4] = {fmaxf(a4.x, 0.f), fmaxf(a4.y, 0.f),
                      fmaxf(a4.z, 0.f), fmaxf(a4.w, 0.f)};
        #pragma unroll
        for (int j = 0; j < 14; j++) {
            const float4 w4 = *(const float4*)(wT + j * DIM + i4 * 4);
            acc[j] = fmaf(a[0], w4.x, acc[j]);
            acc[j] = fmaf(a[1], w4.y, acc[j]);
            acc[j] = fmaf(a[2], w4.z, acc[j]);
            acc[j] = fmaf(a[3], w4.w, acc[j]);
        }
    }
    #pragma unroll
    for (int j = 0; j < 14; j++) {
        #pragma unroll
        for (int off = 16; off; off >>= 1)
            acc[j] += __shfl_down_sync(0xffffffffu, acc[j], off);
    }
    if (lane == 0) {
        float* o = angbuf + (size_t)gw * 14;
        #pragma unroll
        for (int j = 0; j < 14; j++) o[j] = acc[j] + b_ang[j];
    }
}

// ---------------- per-residue geometry ----------------
__global__ __launch_bounds__(128) void epilogue_kernel(
    const float* __restrict__ angbuf,
    const float* __restrict__ rigids, const float* __restrict__ def_frames,
    const float* __restrict__ lit_pos, const float* __restrict__ atom_mask,
    const int* __restrict__ aatype, const int* __restrict__ gidx,
    float* __restrict__ out_angles, float* __restrict__ out_pred,
    float* __restrict__ out_frames)
{
    const int n = blockIdx.x * blockDim.x + threadIdx.x;
    if (n >= NROWS) return;
    const int aa = aatype[n];

    float s[8], c[8];
    s[0] = 0.f; c[0] = 1.f;
    #pragma unroll
    for (int i = 0; i < 7; i++) {
        float ss = angbuf[(size_t)n * 14 + 2 * i];
        float cc = angbuf[(size_t)n * 14 + 2 * i + 1];
        float inv = rsqrtf(fmaxf(ss * ss + cc * cc, 1e-12f));
        ss *= inv; cc *= inv;
        s[i + 1] = ss; c[i + 1] = cc;
        out_angles[(size_t)n * 14 + 2 * i] = ss;
        out_angles[(size_t)n * 14 + 2 * i + 1] = cc;
    }

    float FR[8][9], FT[8][3];
    #pragma unroll
    for (int k = 0; k < 8; k++) {
        const float* D = def_frames + ((size_t)aa * 8 + k) * 16;
        #pragma unroll
        for (int r = 0; r < 3; r++) {
            float d1 = D[r * 4 + 1], d2 = D[r * 4 + 2];
            FR[k][r * 3 + 0] = D[r * 4 + 0];
            FR[k][r * 3 + 1] = c[k] * d1 + s[k] * d2;
            FR[k][r * 3 + 2] = -s[k] * d1 + c[k] * d2;
            FT[k][r] = D[r * 4 + 3];
        }
    }

    #pragma unroll
    for (int k = 5; k <= 7; k++) {
        float R[9], T[3];
        #pragma unroll
        for (int r = 0; r < 3; r++) {
            #pragma unroll
            for (int cc2 = 0; cc2 < 3; cc2++)
                R[r * 3 + cc2] = FR[k - 1][r * 3 + 0] * FR[k][0 + cc2]
                               + FR[k - 1][r * 3 + 1] * FR[k][3 + cc2]
                               + FR[k - 1][r * 3 + 2] * FR[k][6 + cc2];
            T[r] = FR[k - 1][r * 3 + 0] * FT[k][0]
                 + FR[k - 1][r * 3 + 1] * FT[k][1]
                 + FR[k - 1][r * 3 + 2] * FT[k][2] + FT[k - 1][r];
        }
        #pragma unroll
        for (int q = 0; q < 9; q++) FR[k][q] = R[q];
        FT[k][0] = T[0]; FT[k][1] = T[1]; FT[k][2] = T[2];
    }

    const float* rg = rigids + (size_t)n * 16;
    float R0[9] = {rg[0], rg[1], rg[2], rg[4], rg[5], rg[6], rg[8], rg[9], rg[10]};
    float t0[3] = {rg[3], rg[7], rg[11]};

    #pragma unroll
    for (int k = 0; k < 8; k++) {
        float R[9], T[3];
        #pragma unroll
        for (int r = 0; r < 3; r++) {
            #pragma unroll
            for (int cc2 = 0; cc2 < 3; cc2++)
                R[r * 3 + cc2] = R0[r * 3 + 0] * FR[k][0 + cc2]
                               + R0[r * 3 + 1] * FR[k][3 + cc2]
                               + R0[r * 3 + 2] * FR[k][6 + cc2];
            T[r] = R0[r * 3 + 0] * FT[k][0] + R0[r * 3 + 1] * FT[k][1]
                 + R0[r * 3 + 2] * FT[k][2] + t0[r];
        }
        #pragma unroll
        for (int q = 0; q < 9; q++) FR[k][q] = R[q];
        FT[k][0] = T[0]; FT[k][1] = T[1]; FT[k][2] = T[2];

        float* of = out_frames + ((size_t)n * 8 + k) * 16;
        *(float4*)(of + 0)  = make_float4(R[0], R[1], R[2], T[0]);
        *(float4*)(of + 4)  = make_float4(R[3], R[4], R[5], T[1]);
        *(float4*)(of + 8)  = make_float4(R[6], R[7], R[8], T[2]);
        *(float4*)(of + 12) = make_float4(0.f, 0.f, 0.f, 1.f);
    }

    #pragma unroll
    for (int a = 0; a < 14; a++) {
        int g = gidx[aa * 14 + a];
        const float* p = lit_pos + ((size_t)aa * 14 + a) * 3;
        float m = atom_mask[aa * 14 + a];
        float px = p[0], py = p[1], pz = p[2];
        float* op = out_pred + ((size_t)n * 14 + a) * 3;
        op[0] = (FR[g][0] * px + FR[g][1] * py + FR[g][2] * pz + FT[g][0]) * m;
        op[1] = (FR[g][3] * px + FR[g][4] * py + FR[g][5] * pz + FT[g][1]) * m;
        op[2] = (FR[g][6] * px + FR[g][7] * py + FR[g][8] * pz + FT[g][2]) * m;
    }
}

// ---------------- launch ----------------
extern "C" void kernel_launch(void* const* d_in, const int* in_sizes, int n_in,
                              void* d_out, int out_size)
{
    const float* rep0       = (const float*)d_in[0];
    const float* rep1       = (const float*)d_in[1];
    const float* w_in       = (const float*)d_in[2];
    const float* b_in       = (const float*)d_in[3];
    const float* w1         = (const float*)d_in[4];
    const float* b1         = (const float*)d_in[5];
    const float* w2         = (const float*)d_in[6];
    const float* b2         = (const float*)d_in[7];
    const float* w_ang      = (const float*)d_in[8];
    const float* b_ang      = (const float*)d_in[9];
    const float* rigids     = (const float*)d_in[10];
    const float* def_frames = (const float*)d_in[11];
    const float* lit_pos    = (const float*)d_in[12];
    const float* atom_mask  = (const float*)d_in[13];
    const int*   aatype     = (const int*)d_in[14];
    const int*   gidx       = (const int*)d_in[15];

    float *act, *angb, *wangT;
    __half *wt, *sah, *sbh;
    cudaGetSymbolAddress((void**)&act, g_act);
    cudaGetSymbolAddress((void**)&angb, g_ang);
    cudaGetSymbolAddress((void**)&wangT, g_wangT);
    cudaGetSymbolAddress((void**)&wt, g_wt);
    cudaGetSymbolAddress((void**)&sah, g_sa_hi);
    cudaGetSymbolAddress((void**)&sbh, g_sb_hi);
    const size_t WSZ = (size_t)DIM * DIM;

    cudaFuncSetAttribute(gemm_mma<0,1,1>, cudaFuncAttributeMaxDynamicSharedMemorySize, SMEM_TOTAL);
    cudaFuncSetAttribute(gemm_mma<0,0,1>, cudaFuncAttributeMaxDynamicSharedMemorySize, SMEM_TOTAL);
    cudaFuncSetAttribute(gemm_mma<1,1,1>, cudaFuncAttributeMaxDynamicSharedMemorySize, SMEM_TOTAL);
    cudaFuncSetAttribute(gemm_mma<1,1,0>, cudaFuncAttributeMaxDynamicSharedMemorySize, SMEM_TOTAL);

    dim3 pg(DIM / 32, DIM / 32), pb(32, 8);
    prep_w<<<pg, pb>>>(w_in, wt + 0 * WSZ);
    prep_w<<<pg, pb>>>(w1,   wt + 1 * WSZ);
    prep_w<<<pg, pb>>>(w2,   wt + 2 * WSZ);
    prep_wang<<<(14 * DIM + 255) / 256, 256>>>(w_ang, wangT);

    fuse0<<<(NROWS * DIM) / (256 * 4), 256>>>(rep0, rep1, sah);

    dim3 grid(DIM / 128, NROWS / 128);  // (8, 256)

    gemm_mma<0,1,1><<<grid, 256, SMEM_TOTAL>>>(sah, wt + 0*WSZ, b_in, 2.f, act, sbh);
    gemm_mma<0,0,1><<<grid, 256, SMEM_TOTAL>>>(sbh, wt + 1*WSZ, b1, 1.f, act, sah);
    gemm_mma<1,1,1><<<grid, 256, SMEM_TOTAL>>>(sah, wt + 2*WSZ, b2, 1.f, act, sbh);
    gemm_mma<0,0,1><<<grid, 256, SMEM_TOTAL>>>(sbh, wt + 1*WSZ, b1, 1.f, act, sah);
    gemm_mma<1,1,0><<<grid, 256, SMEM_TOTAL>>>(sah, wt + 2*WSZ, b2, 1.f, act, sbh);

    ang_kernel<<<NROWS / 8, 256>>>(act, wangT, b_ang, angb);

    float* out = (float*)d_out;
    float* out_angles = out;
    float* out_pred   = out + (size_t)NROWS * 14;
    float* out_frames = out + (size_t)NROWS * 56;
    epilogue_kernel<<<(NROWS + 127) / 128, 128>>>(
        angb, rigids, def_frames, lit_pos, atom_mask, aatype, gidx,
        out_angles, out_pred, out_frames);
}